// round 7
// baseline (speedup 1.0000x reference)
#include <cuda_runtime.h>
#include <cuda_fp16.h>
#include <cstdint>
#include <math.h>

#define B_  8
#define S_  1024
#define D_  1024
#define H_  16
#define E_  64
#define HE_ 1024
#define BS_ (B_*S_)
#define NT_ (S_/64)
#define KP_ 2048          // packed K for projections: [Xh | Xl] x [Wh | Wh]

// ---------------- scratch (device globals; no runtime allocation) ----------
__device__ float g_V [B_*S_*HE_];
__device__ float g_TS[B_*H_*NT_*E_];
__device__ float g_P [B_*H_*(NT_+1)*E_];

// packed fp16 operands for projection GEMMs (K folded x2)
__device__ __half g_X1p[(size_t)BS_*KP_];
__device__ __half g_X2p[(size_t)BS_*KP_];
__device__ __half g_AOp[(size_t)BS_*KP_];
__device__ __half g_Wqp[(size_t)HE_*KP_];
__device__ __half g_Wkp[(size_t)HE_*KP_];
__device__ __half g_Wvp[(size_t)HE_*KP_];
__device__ __half g_Wop[(size_t)HE_*KP_];

// per-head fp16 operands for attention mma
__device__ __half g_Qh[(size_t)B_*H_*S_*E_], g_Ql[(size_t)B_*H_*S_*E_];  // [bh][s][e]
__device__ __half g_Kh[(size_t)B_*H_*S_*E_];                             // [bh][s][e]
__device__ __half g_Vth[(size_t)B_*H_*E_*S_];                            // [bh][e][s]
__device__ __half g_Ah[(size_t)B_*H_*S_*S_], g_Al[(size_t)B_*H_*S_*S_];  // [bh][q][k]

// ---------------- PTX helpers (baseline sm_80+) -----------------------------
__device__ __forceinline__ uint32_t smem_u32(const void* p) {
    uint32_t a;
    asm("{ .reg .u64 t; cvta.to.shared.u64 t, %1; cvt.u32.u64 %0, t; }" : "=r"(a) : "l"(p));
    return a;
}
__device__ __forceinline__ void cp16(uint32_t s, const void* g) {
    asm volatile("cp.async.cg.shared.global [%0], [%1], 16;" :: "r"(s), "l"(g));
}
#define CP_COMMIT() asm volatile("cp.async.commit_group;" ::: "memory")
#define CP_WAIT1()  asm volatile("cp.async.wait_group 1;" ::: "memory")
#define CP_WAIT0()  asm volatile("cp.async.wait_group 0;" ::: "memory")

#define LDSM4(r, a) \
    asm volatile("ldmatrix.sync.aligned.m8n8.x4.shared.b16 {%0,%1,%2,%3}, [%4];" \
        : "=r"((r)[0]), "=r"((r)[1]), "=r"((r)[2]), "=r"((r)[3]) : "r"(a))

#define MMAF16(c, a, b0v, b1v) \
    asm volatile("mma.sync.aligned.m16n8k16.row.col.f32.f16.f16.f32 " \
        "{%0,%1,%2,%3}, {%4,%5,%6,%7}, {%8,%9}, {%0,%1,%2,%3};" \
        : "+f"((c)[0]), "+f"((c)[1]), "+f"((c)[2]), "+f"((c)[3]) \
        : "r"((a)[0]), "r"((a)[1]), "r"((a)[2]), "r"((a)[3]), "r"(b0v), "r"(b1v))

// ---------------- pack kernels ---------------------------------------------
__global__ __launch_bounds__(256) void pack_x_kernel(
    const float* __restrict__ in, __half* __restrict__ out, int n4)
{
    int i = blockIdx.x * 256 + threadIdx.x;
    if (i >= n4) return;
    const int row = i >> 8;
    const int c   = (i & 255) * 4;
    float4 v = ((const float4*)in)[i];
    float f[4] = {v.x, v.y, v.z, v.w};
    __half hh[4], ll[4];
    #pragma unroll
    for (int j = 0; j < 4; j++) {
        hh[j] = __float2half_rn(f[j]);
        ll[j] = __float2half_rn(f[j] - __half2float(hh[j]));
    }
    __half* base = out + (size_t)row * KP_;
    *(__half2*)(base + c)          = __half2(hh[0], hh[1]);
    *(__half2*)(base + c + 2)      = __half2(hh[2], hh[3]);
    *(__half2*)(base + 1024 + c)   = __half2(ll[0], ll[1]);
    *(__half2*)(base + 1024 + c+2) = __half2(ll[2], ll[3]);
}

__global__ __launch_bounds__(256) void pack_w_kernel(
    const float* __restrict__ W, __half* __restrict__ out)
{
    __shared__ float t[32][33];
    const int n0 = blockIdx.x * 32, k0 = blockIdx.y * 32;
    const int tx = threadIdx.x, ty = threadIdx.y;
    #pragma unroll
    for (int i = 0; i < 4; i++)
        t[ty + i*8][tx] = W[(size_t)(k0 + ty + i*8) * 1024 + n0 + tx];
    __syncthreads();
    #pragma unroll
    for (int i = 0; i < 4; i++) {
        float v = t[tx][ty + i*8];
        __half h = __float2half_rn(v);
        size_t o = (size_t)(n0 + ty + i*8) * KP_ + k0 + tx;
        out[o]        = h;
        out[o + 1024] = h;
    }
}

// ---------------- projection GEMM (mma.sync fp16, K-fold x2) ---------------
__global__ __launch_bounds__(256) void gemm_mma_kernel(
    const __half* __restrict__ Ap, const __half* __restrict__ Bp,
    const float* __restrict__ bias, float* __restrict__ C,
    __half* __restrict__ Oh, __half* __restrict__ Ol, int mode)
{
    extern __shared__ char smch[];
    const uint32_t sb = smem_u32(smch);
    const int tid = threadIdx.x;
    const int lane = tid & 31, wid = tid >> 5;
    const int wm = wid >> 2, wn = wid & 3;
    const size_t m0 = (size_t)blockIdx.y * 128;
    const size_t n0 = (size_t)blockIdx.x * 128;

    const int lr = tid >> 2;
    const int lco = (tid & 3) * 16;
    const __half* gA0 = Ap + (m0 + lr) * KP_ + (tid & 3) * 8;
    const __half* gB0 = Bp + (n0 + lr) * KP_ + (tid & 3) * 8;
    const uint32_t smA = sb + lr * 80 + lco;
    const uint32_t smB = smA + 10240;

    float acc[4][4][4];
    #pragma unroll
    for (int a = 0; a < 4; a++)
        #pragma unroll
        for (int b = 0; b < 4; b++)
            #pragma unroll
            for (int c = 0; c < 4; c++) acc[a][b][c] = 0.f;

    #define LOADST(kt, st) do {                                        \
        const uint32_t so_ = (uint32_t)(st) * 20480u;                  \
        const __half* ga_ = gA0 + (kt) * 32;                           \
        const __half* gb_ = gB0 + (kt) * 32;                           \
        cp16(smA + so_,           ga_);                                \
        cp16(smA + so_ + 64*80,   ga_ + (size_t)64 * KP_);             \
        cp16(smB + so_,           gb_);                                \
        cp16(smB + so_ + 64*80,   gb_ + (size_t)64 * KP_);             \
        CP_COMMIT();                                                   \
    } while (0)

    LOADST(0, 0);
    LOADST(1, 1);

    const uint32_t aAddr = sb + (uint32_t)(wm*64 + (lane & 15)) * 80 + ((lane >> 4) << 4);
    const uint32_t bAddr = sb + 10240 +
        (uint32_t)(wn*32 + ((lane >> 3) & 1) * 8 + (lane & 7)) * 80 + ((lane >> 4) << 4);

    const int NKT = KP_ / 32;   // 64
    #pragma unroll 1
    for (int kt = 0; kt < NKT; kt++) {
        const int st = kt % 3;
        CP_WAIT1();
        __syncthreads();
        if (kt + 2 < NKT) LOADST(kt + 2, (kt + 2) % 3);
        const uint32_t so = (uint32_t)st * 20480u;
        #pragma unroll
        for (int ks = 0; ks < 2; ks++) {
            uint32_t afr[4][4], bfr[2][4];
            #pragma unroll
            for (int mt = 0; mt < 4; mt++)
                LDSM4(afr[mt], aAddr + so + (uint32_t)mt*16*80 + ks*32);
            #pragma unroll
            for (int nt2 = 0; nt2 < 2; nt2++)
                LDSM4(bfr[nt2], bAddr + so + (uint32_t)nt2*16*80 + ks*32);
            #pragma unroll
            for (int mt = 0; mt < 4; mt++)
                #pragma unroll
                for (int nt = 0; nt < 4; nt++)
                    MMAF16(acc[mt][nt], afr[mt],
                           bfr[nt >> 1][nt & 1], bfr[nt >> 1][2 + (nt & 1)]);
        }
    }
    CP_WAIT0();

    const int crow = lane >> 2, ccol = (lane & 3) * 2;
    if (mode == 0) {
        #pragma unroll
        for (int nt = 0; nt < 4; nt++) {
            const int n = (int)n0 + wn*32 + nt*8 + ccol;
            const float b0v = bias[n], b1v = bias[n + 1];
            #pragma unroll
            for (int mt = 0; mt < 4; mt++) {
                const size_t m = m0 + wm*64 + mt*16 + crow;
                float2 v0, v1;
                v0.x = acc[mt][nt][0] + b0v; v0.y = acc[mt][nt][1] + b1v;
                v1.x = acc[mt][nt][2] + b0v; v1.y = acc[mt][nt][3] + b1v;
                *(float2*)(C + m * 1024 + n)       = v0;
                *(float2*)(C + (m + 8) * 1024 + n) = v1;
            }
        }
    } else {
        #pragma unroll
        for (int nt = 0; nt < 4; nt++) {
            const int n = (int)n0 + wn*32 + nt*8 + ccol;
            const float b0v = bias[n], b1v = bias[n + 1];
            const int h = n >> 6, e = n & 63;
            #pragma unroll
            for (int mt = 0; mt < 4; mt++) {
                #pragma unroll
                for (int half = 0; half < 2; half++) {
                    const size_t m = m0 + wm*64 + mt*16 + crow + half*8;
                    const int b2 = (int)(m >> 10), s = (int)(m & 1023);
                    const size_t o = (((size_t)(b2*16 + h) * 1024 + s) * 64 + e);
                    const float v0 = acc[mt][nt][half*2]     + b0v;
                    const float v1 = acc[mt][nt][half*2 + 1] + b1v;
                    const __half h0 = __float2half_rn(v0);
                    const __half h1 = __float2half_rn(v1);
                    *(__half2*)(Oh + o) = __half2(h0, h1);
                    if (mode == 1) {
                        const __half l0 = __float2half_rn(v0 - __half2float(h0));
                        const __half l1 = __float2half_rn(v1 - __half2float(h1));
                        *(__half2*)(Ol + o) = __half2(l0, l1);
                    }
                }
            }
        }
    }
    #undef LOADST
}

// ---------------- V fp32 -> transposed per-head fp16 hi --------------------
__global__ void cvt_vt_kernel()
{
    __shared__ float t[32][33];
    const int bh = blockIdx.z;
    const int b = bh >> 4, h = bh & 15;
    const int s0 = blockIdx.y * 32, e0 = blockIdx.x * 32;
    const int tx = threadIdx.x, ty = threadIdx.y;
    #pragma unroll
    for (int i = 0; i < 4; i++)
        t[ty + i*8][tx] = g_V[((size_t)(b*1024) + s0 + ty + i*8) * 1024 + h*64 + e0 + tx];
    __syncthreads();
    #pragma unroll
    for (int i = 0; i < 4; i++) {
        const float v = t[tx][ty + i*8];
        g_Vth[((size_t)bh * 64 + e0 + ty + i*8) * 1024 + s0 + tx] = __float2half_rn(v);
    }
}

// ---------------- fused scores + head-softmax ------------------------------
// grid (kt2, qt, b), kt2 = 32-wide k half-tiles, block 256 (8 warps: 4q x 2k)
// smem: scores fp32 [16][64][32] (128KB) + Qh/Ql (9216B each) + Kh (4608B)
#define ATT_SCORES 131072u
#define ATT_QH (ATT_SCORES)
#define ATT_QL (ATT_QH + 9216u)
#define ATT_KH (ATT_QL + 9216u)
#define SMEM_ATT (ATT_KH + 4608u)

__global__ __launch_bounds__(256) void attn_scores_softmax_kernel()
{
    const int kt2 = blockIdx.x, qt = blockIdx.y, b = blockIdx.z;
    if (kt2 > 2*qt + 1) return;

    extern __shared__ char sm[];
    float* sS = (float*)sm;
    const uint32_t uQH = smem_u32(sm + ATT_QH);
    const uint32_t uQL = smem_u32(sm + ATT_QL);
    const uint32_t uKH = smem_u32(sm + ATT_KH);

    const int tid = threadIdx.x, lane = tid & 31, wid = tid >> 5;
    const int wm = wid >> 1, wn = wid & 1;

    const uint32_t aOff = (uint32_t)(wm*16 + (lane & 15)) * 144 + ((lane >> 4) << 4);
    const uint32_t bOff = (uint32_t)(wn*16 + ((lane >> 3) & 1)*8 + (lane & 7)) * 144 + ((lane >> 4) << 4);
    const int crow = lane >> 2, ccol = (lane & 3) * 2;
    const float scale = 0.35355339059327373f;   // 1/sqrt(8) batch-size quirk

    #pragma unroll 1
    for (int h = 0; h < 16; h++) {
        const int bh = b*16 + h;
        const __half* gQH = g_Qh + ((size_t)bh * 1024 + qt*64) * 64;
        const __half* gQL = g_Ql + ((size_t)bh * 1024 + qt*64) * 64;
        const __half* gKH = g_Kh + ((size_t)bh * 1024 + kt2*32) * 64;

        __syncthreads();   // previous head's tiles fully consumed
        #pragma unroll
        for (int i = tid; i < 512; i += 256) {
            const int r = i >> 3, c = i & 7;
            const size_t go = (size_t)r * 64 + c * 8;
            const uint32_t so = r * 144 + c * 16;
            *(uint4*)(sm + ATT_QH + so) = *(const uint4*)(gQH + go);
            *(uint4*)(sm + ATT_QL + so) = *(const uint4*)(gQL + go);
        }
        {
            const int r = tid >> 3, c = tid & 7;   // 32 rows x 8 chunks = 256
            *(uint4*)(sm + ATT_KH + r*144 + c*16) = *(const uint4*)(gKH + (size_t)r*64 + c*8);
        }
        __syncthreads();

        float acc[2][4];
        #pragma unroll
        for (int n = 0; n < 2; n++)
            #pragma unroll
            for (int c = 0; c < 4; c++) acc[n][c] = 0.f;

        #pragma unroll
        for (int es = 0; es < 4; es++) {
            uint32_t ah[4], al[4], bv[4];
            LDSM4(ah, uQH + aOff + es*32);
            LDSM4(al, uQL + aOff + es*32);
            LDSM4(bv, uKH + bOff + es*32);
            #pragma unroll
            for (int n = 0; n < 2; n++) {
                MMAF16(acc[n], ah, bv[n], bv[2 + n]);
                MMAF16(acc[n], al, bv[n], bv[2 + n]);
            }
        }

        // scale + causal mask + exact-zero quirk, park in smem (fp32)
        #pragma unroll
        for (int n = 0; n < 2; n++) {
            #pragma unroll
            for (int half = 0; half < 2; half++) {
                const int q = wm*16 + crow + half*8;
                const int k = wn*16 + n*8 + ccol;
                const int gq = qt*64 + q, gk = kt2*32 + k;
                float v0 = acc[n][half*2]     * scale;
                float v1 = acc[n][half*2 + 1] * scale;
                if (gk     > gq || v0 == 0.0f) v0 = -1e9f;
                if (gk + 1 > gq || v1 == 0.0f) v1 = -1e9f;
                *(float2*)&sS[h*2048 + q*32 + k] = make_float2(v0, v1);
            }
        }
    }
    __syncthreads();

    // softmax over the 16 heads, emit fp16 hi/lo attn operands
    #pragma unroll 1
    for (int i = tid; i < 1024; i += 256) {
        const int q = i >> 4, kk = (i & 15) * 2;
        float2 sv[16];
        float m0 = -3.4e38f, m1 = -3.4e38f;
        #pragma unroll
        for (int h = 0; h < 16; h++) {
            sv[h] = *(float2*)&sS[h*2048 + q*32 + kk];
            m0 = fmaxf(m0, sv[h].x);
            m1 = fmaxf(m1, sv[h].y);
        }
        float Z0 = 0.f, Z1 = 0.f;
        #pragma unroll
        for (int h = 0; h < 16; h++) {
            sv[h].x = expf(sv[h].x - m0); Z0 += sv[h].x;
            sv[h].y = expf(sv[h].y - m1); Z1 += sv[h].y;
        }
        const float i0 = 1.0f / Z0, i1 = 1.0f / Z1;
        const size_t base0 = (((size_t)(b*16) * 1024 + qt*64 + q) * 1024) + kt2*32 + kk;
        #pragma unroll
        for (int h = 0; h < 16; h++) {
            const float a0 = sv[h].x * i0, a1 = sv[h].y * i1;
            const __half h0 = __float2half_rn(a0);
            const __half h1 = __float2half_rn(a1);
            const __half l0 = __float2half_rn(a0 - __half2float(h0));
            const __half l1 = __float2half_rn(a1 - __half2float(h1));
            const size_t o = base0 + (size_t)h * 1024 * 1024;
            *(__half2*)(g_Ah + o) = __half2(h0, h1);
            *(__half2*)(g_Al + o) = __half2(l0, l1);
        }
    }
}

// ---------------- V tile sums + prefix scan --------------------------------
__global__ void tilesum_kernel()
{
    const int blk = blockIdx.x;
    const int e = threadIdx.x;
    const int tt = blk & (NT_ - 1);
    const int bh = blk / NT_;
    const int b = bh >> 4, h = bh & 15;
    const float* Vb = g_V + ((size_t)(b*S_ + tt*64)) * HE_ + h*64 + e;
    float sum = 0.f;
    #pragma unroll 8
    for (int k = 0; k < 64; k++) sum += Vb[(size_t)k * HE_];
    g_TS[((size_t)bh * NT_ + tt) * E_ + e] = sum;
}

__global__ void scan_kernel()
{
    const int id = blockIdx.x * 256 + threadIdx.x;
    const int e = id & 63, bh = id >> 6;
    float* P = g_P + (size_t)bh * (NT_ + 1) * E_;
    float p = 0.f;
    P[e] = 0.f;
    #pragma unroll
    for (int tt = 0; tt < NT_; tt++) {
        p += g_TS[((size_t)bh * NT_ + tt) * E_ + e];
        P[(tt + 1) * E_ + e] = p;
    }
}

// ---------------- attn @ V via mma (fp16 x2) + masked suffix ---------------
__global__ __launch_bounds__(128) void attnv_mma_kernel()
{
    const int qt = blockIdx.x, bh = blockIdx.y;
    const int b = bh >> 4, h = bh & 15;

    __shared__ __align__(16) char sm[3 * 64 * 144];
    const uint32_t sAH = smem_u32(sm);
    const uint32_t sAL = sAH +  9216;
    const uint32_t sVH = sAH + 18432;

    const int tid = threadIdx.x;
    const int lane = tid & 31, wid = tid >> 5;
    const int wm = wid >> 1, wn = wid & 1;

    float acc[2][4][4];
    #pragma unroll
    for (int a = 0; a < 2; a++)
        #pragma unroll
        for (int b2 = 0; b2 < 4; b2++)
            #pragma unroll
            for (int c = 0; c < 4; c++) acc[a][b2][c] = 0.f;

    const uint32_t aOff = (uint32_t)(wm*32 + (lane & 15)) * 144 + ((lane >> 4) << 4);
    const uint32_t bOff = (uint32_t)(wn*32 + ((lane >> 3) & 1)*8 + (lane & 7)) * 144 + ((lane >> 4) << 4);

    const __half* gAH0 = g_Ah + ((size_t)bh * 1024 + qt*64) * 1024;
    const __half* gAL0 = g_Al + ((size_t)bh * 1024 + qt*64) * 1024;
    const __half* gVH0 = g_Vth + (size_t)bh * 64 * 1024;

    for (int kt = 0; kt <= qt; kt++) {
        __syncthreads();
        #pragma unroll
        for (int i = tid; i < 512; i += 128) {
            const int r = i >> 3, c = i & 7;
            const size_t go = (size_t)r * 1024 + kt*64 + c * 8;
            const uint32_t so = r * 144 + c * 16;
            *(uint4*)(sm + so)         = *(const uint4*)(gAH0 + go);
            *(uint4*)(sm + 9216 + so)  = *(const uint4*)(gAL0 + go);
            *(uint4*)(sm + 18432 + so) = *(const uint4*)(gVH0 + go);
        }
        __syncthreads();

        #pragma unroll
        for (int ks = 0; ks < 4; ks++) {
            const uint32_t cb = ks * 32;
            uint32_t ah[2][4], al[2][4], vh[2][4];
            #pragma unroll
            for (int mt = 0; mt < 2; mt++) {
                LDSM4(ah[mt], sAH + aOff + (uint32_t)mt*16*144 + cb);
                LDSM4(al[mt], sAL + aOff + (uint32_t)mt*16*144 + cb);
            }
            #pragma unroll
            for (int nt2 = 0; nt2 < 2; nt2++)
                LDSM4(vh[nt2], sVH + bOff + (uint32_t)nt2*16*144 + cb);
            #pragma unroll
            for (int mt = 0; mt < 2; mt++)
                #pragma unroll
                for (int nt = 0; nt < 4; nt++) {
                    MMAF16(acc[mt][nt], ah[mt], vh[nt>>1][nt&1], vh[nt>>1][2+(nt&1)]);
                    MMAF16(acc[mt][nt], al[mt], vh[nt>>1][nt&1], vh[nt>>1][2+(nt&1)]);
                }
        }
    }

    const float* P = g_P + (size_t)bh * (NT_ + 1) * E_;
    #pragma unroll
    for (int nt = 0; nt < 4; nt++) {
        const int e0 = wn*32 + nt*8 + (lane & 3)*2;
        const float s0 = (P[NT_*E_ + e0]     - P[(qt+1)*E_ + e0])     * 0.0625f;
        const float s1 = (P[NT_*E_ + e0 + 1] - P[(qt+1)*E_ + e0 + 1]) * 0.0625f;
        #pragma unroll
        for (int mt = 0; mt < 2; mt++) {
            #pragma unroll
            for (int half = 0; half < 2; half++) {
                const int q = wm*32 + mt*16 + (lane >> 2) + half*8;
                const float v0 = acc[mt][nt][half*2]     + s0;
                const float v1 = acc[mt][nt][half*2 + 1] + s1;
                const __half h0 = __float2half_rn(v0);
                const __half h1 = __float2half_rn(v1);
                const __half l0 = __float2half_rn(v0 - __half2float(h0));
                const __half l1 = __float2half_rn(v1 - __half2float(h1));
                __half* base = g_AOp + ((size_t)(b*1024 + qt*64 + q)) * KP_ + h*64 + e0;
                *(__half2*)(base)        = __half2(h0, h1);
                *(__half2*)(base + 1024) = __half2(l0, l1);
            }
        }
    }
}

// ---------------- launch ---------------------------------------------------
extern "C" void kernel_launch(void* const* d_in, const int* in_sizes, int n_in,
                              void* d_out, int out_size)
{
    const float* X1 = (const float*)d_in[0];
    const float* X2 = (const float*)d_in[1];
    const float* Wq = (const float*)d_in[2];
    const float* bq = (const float*)d_in[3];
    const float* Wk = (const float*)d_in[4];
    const float* bk = (const float*)d_in[5];
    const float* Wv = (const float*)d_in[6];
    const float* bv = (const float*)d_in[7];
    const float* Wo = (const float*)d_in[8];
    const float* bo = (const float*)d_in[9];
    float* out = (float*)d_out;

    void *pV;
    void *pX1p, *pX2p, *pAOp, *pWqp, *pWkp, *pWvp, *pWop;
    void *pQh, *pQl, *pKh;
    cudaGetSymbolAddress(&pV,  g_V);
    cudaGetSymbolAddress(&pX1p, g_X1p); cudaGetSymbolAddress(&pX2p, g_X2p);
    cudaGetSymbolAddress(&pAOp, g_AOp);
    cudaGetSymbolAddress(&pWqp, g_Wqp); cudaGetSymbolAddress(&pWkp, g_Wkp);
    cudaGetSymbolAddress(&pWvp, g_Wvp); cudaGetSymbolAddress(&pWop, g_Wop);
    cudaGetSymbolAddress(&pQh, g_Qh);   cudaGetSymbolAddress(&pQl, g_Ql);
    cudaGetSymbolAddress(&pKh, g_Kh);

    const uint32_t SMEM_G = 61440;
    cudaFuncSetAttribute(gemm_mma_kernel,
                         cudaFuncAttributeMaxDynamicSharedMemorySize, SMEM_G);
    cudaFuncSetAttribute(attn_scores_softmax_kernel,
                         cudaFuncAttributeMaxDynamicSharedMemorySize, SMEM_ATT);

    const int n4x = BS_ * D_ / 4;
    pack_x_kernel<<<n4x / 256, 256>>>(X1, (__half*)pX1p, n4x);
    pack_x_kernel<<<n4x / 256, 256>>>(X2, (__half*)pX2p, n4x);

    const dim3 gT(32, 32), bT(32, 8);
    pack_w_kernel<<<gT, bT>>>(Wq, (__half*)pWqp);
    pack_w_kernel<<<gT, bT>>>(Wk, (__half*)pWkp);
    pack_w_kernel<<<gT, bT>>>(Wv, (__half*)pWvp);
    pack_w_kernel<<<gT, bT>>>(Wo, (__half*)pWop);

    const dim3 gG(HE_ / 128, BS_ / 128);
    gemm_mma_kernel<<<gG, 256, SMEM_G>>>((__half*)pX1p, (__half*)pWqp, bq,
                                         nullptr, (__half*)pQh, (__half*)pQl, 1);
    gemm_mma_kernel<<<gG, 256, SMEM_G>>>((__half*)pX2p, (__half*)pWkp, bk,
                                         nullptr, (__half*)pKh, nullptr, 2);
    gemm_mma_kernel<<<gG, 256, SMEM_G>>>((__half*)pX2p, (__half*)pWvp, bv,
                                         (float*)pV, nullptr, nullptr, 0);

    cvt_vt_kernel<<<dim3(2, 32, B_*H_), dim3(32, 8)>>>();
    tilesum_kernel<<<B_ * H_ * NT_, 64>>>();
    scan_kernel<<<(B_ * H_ * E_) / 256, 256>>>();

    // fused scores + head-softmax (no fp32 score tensor in DRAM)
    attn_scores_softmax_kernel<<<dim3(2*NT_, NT_, B_), 256, SMEM_ATT>>>();

    attnv_mma_kernel<<<dim3(NT_, B_ * H_), 128>>>();

    gemm_mma_kernel<<<gG, 256, SMEM_G>>>((__half*)pAOp, (__half*)pWop, bo,
                                         out, nullptr, nullptr, 0);
}

// round 8
// speedup vs baseline: 1.2022x; 1.2022x over previous
#include <cuda_runtime.h>
#include <cuda_fp16.h>
#include <cstdint>
#include <math.h>

#define B_  8
#define S_  1024
#define D_  1024
#define H_  16
#define E_  64
#define HE_ 1024
#define BS_ (B_*S_)
#define NT_ (S_/64)
#define KP_ 2048          // packed K for projections: [Xh | Xl] x [Wh | Wh]

// ---------------- scratch (device globals; no runtime allocation) ----------
__device__ float g_V [B_*S_*HE_];
__device__ float g_Sc[(size_t)B_*H_*S_*S_];
__device__ float g_TS[B_*H_*NT_*E_];
__device__ float g_P [B_*H_*(NT_+1)*E_];

// packed fp16 operands for projection GEMMs (K folded x2)
__device__ __half g_X1p[(size_t)BS_*KP_];
__device__ __half g_X2p[(size_t)BS_*KP_];
__device__ __half g_AOp[(size_t)BS_*KP_];
__device__ __half g_Wqp[(size_t)HE_*KP_];
__device__ __half g_Wkp[(size_t)HE_*KP_];
__device__ __half g_Wvp[(size_t)HE_*KP_];
__device__ __half g_Wop[(size_t)HE_*KP_];

// per-head fp16 operands for attention mma
__device__ __half g_Qh[(size_t)B_*H_*S_*E_], g_Ql[(size_t)B_*H_*S_*E_];  // [bh][s][e]
__device__ __half g_Kh[(size_t)B_*H_*S_*E_];                             // [bh][s][e]
__device__ __half g_Vth[(size_t)B_*H_*E_*S_];                            // [bh][e][s]
__device__ __half g_Ah[(size_t)B_*H_*S_*S_];                             // [bh][q][k] (hi only)

// ---------------- PTX helpers (baseline sm_80+) -----------------------------
__device__ __forceinline__ uint32_t smem_u32(const void* p) {
    uint32_t a;
    asm("{ .reg .u64 t; cvta.to.shared.u64 t, %1; cvt.u32.u64 %0, t; }" : "=r"(a) : "l"(p));
    return a;
}
__device__ __forceinline__ void cp16(uint32_t s, const void* g) {
    asm volatile("cp.async.cg.shared.global [%0], [%1], 16;" :: "r"(s), "l"(g));
}
#define CP_COMMIT() asm volatile("cp.async.commit_group;" ::: "memory")
#define CP_WAIT1()  asm volatile("cp.async.wait_group 1;" ::: "memory")
#define CP_WAIT0()  asm volatile("cp.async.wait_group 0;" ::: "memory")

#define LDSM4(r, a) \
    asm volatile("ldmatrix.sync.aligned.m8n8.x4.shared.b16 {%0,%1,%2,%3}, [%4];" \
        : "=r"((r)[0]), "=r"((r)[1]), "=r"((r)[2]), "=r"((r)[3]) : "r"(a))

#define MMAF16(c, a, b0v, b1v) \
    asm volatile("mma.sync.aligned.m16n8k16.row.col.f32.f16.f16.f32 " \
        "{%0,%1,%2,%3}, {%4,%5,%6,%7}, {%8,%9}, {%0,%1,%2,%3};" \
        : "+f"((c)[0]), "+f"((c)[1]), "+f"((c)[2]), "+f"((c)[3]) \
        : "r"((a)[0]), "r"((a)[1]), "r"((a)[2]), "r"((a)[3]), "r"(b0v), "r"(b1v))

// ---------------- pack kernels ---------------------------------------------
__global__ __launch_bounds__(256) void pack_x_kernel(
    const float* __restrict__ in, __half* __restrict__ out, int n4)
{
    int i = blockIdx.x * 256 + threadIdx.x;
    if (i >= n4) return;
    const int row = i >> 8;
    const int c   = (i & 255) * 4;
    float4 v = ((const float4*)in)[i];
    float f[4] = {v.x, v.y, v.z, v.w};
    __half hh[4], ll[4];
    #pragma unroll
    for (int j = 0; j < 4; j++) {
        hh[j] = __float2half_rn(f[j]);
        ll[j] = __float2half_rn(f[j] - __half2float(hh[j]));
    }
    __half* base = out + (size_t)row * KP_;
    *(__half2*)(base + c)          = __half2(hh[0], hh[1]);
    *(__half2*)(base + c + 2)      = __half2(hh[2], hh[3]);
    *(__half2*)(base + 1024 + c)   = __half2(ll[0], ll[1]);
    *(__half2*)(base + 1024 + c+2) = __half2(ll[2], ll[3]);
}

__global__ __launch_bounds__(256) void pack_w_kernel(
    const float* __restrict__ W, __half* __restrict__ out)
{
    __shared__ float t[32][33];
    const int n0 = blockIdx.x * 32, k0 = blockIdx.y * 32;
    const int tx = threadIdx.x, ty = threadIdx.y;
    #pragma unroll
    for (int i = 0; i < 4; i++)
        t[ty + i*8][tx] = W[(size_t)(k0 + ty + i*8) * 1024 + n0 + tx];
    __syncthreads();
    #pragma unroll
    for (int i = 0; i < 4; i++) {
        float v = t[tx][ty + i*8];
        __half h = __float2half_rn(v);
        size_t o = (size_t)(n0 + ty + i*8) * KP_ + k0 + tx;
        out[o]        = h;
        out[o + 1024] = h;
    }
}

// ---------------- projection GEMM (mma.sync fp16, K-fold x2) ---------------
__global__ __launch_bounds__(256) void gemm_mma_kernel(
    const __half* __restrict__ Ap, const __half* __restrict__ Bp,
    const float* __restrict__ bias, float* __restrict__ C,
    __half* __restrict__ Oh, __half* __restrict__ Ol, int mode)
{
    extern __shared__ char smch[];
    const uint32_t sb = smem_u32(smch);
    const int tid = threadIdx.x;
    const int lane = tid & 31, wid = tid >> 5;
    const int wm = wid >> 2, wn = wid & 3;
    const size_t m0 = (size_t)blockIdx.y * 128;
    const size_t n0 = (size_t)blockIdx.x * 128;

    const int lr = tid >> 2;
    const int lco = (tid & 3) * 16;
    const __half* gA0 = Ap + (m0 + lr) * KP_ + (tid & 3) * 8;
    const __half* gB0 = Bp + (n0 + lr) * KP_ + (tid & 3) * 8;
    const uint32_t smA = sb + lr * 80 + lco;
    const uint32_t smB = smA + 10240;

    float acc[4][4][4];
    #pragma unroll
    for (int a = 0; a < 4; a++)
        #pragma unroll
        for (int b = 0; b < 4; b++)
            #pragma unroll
            for (int c = 0; c < 4; c++) acc[a][b][c] = 0.f;

    #define LOADST(kt, st) do {                                        \
        const uint32_t so_ = (uint32_t)(st) * 20480u;                  \
        const __half* ga_ = gA0 + (kt) * 32;                           \
        const __half* gb_ = gB0 + (kt) * 32;                           \
        cp16(smA + so_,           ga_);                                \
        cp16(smA + so_ + 64*80,   ga_ + (size_t)64 * KP_);             \
        cp16(smB + so_,           gb_);                                \
        cp16(smB + so_ + 64*80,   gb_ + (size_t)64 * KP_);             \
        CP_COMMIT();                                                   \
    } while (0)

    LOADST(0, 0);
    LOADST(1, 1);

    const uint32_t aAddr = sb + (uint32_t)(wm*64 + (lane & 15)) * 80 + ((lane >> 4) << 4);
    const uint32_t bAddr = sb + 10240 +
        (uint32_t)(wn*32 + ((lane >> 3) & 1) * 8 + (lane & 7)) * 80 + ((lane >> 4) << 4);

    const int NKT = KP_ / 32;   // 64
    #pragma unroll 1
    for (int kt = 0; kt < NKT; kt++) {
        const int st = kt % 3;
        CP_WAIT1();
        __syncthreads();
        if (kt + 2 < NKT) LOADST(kt + 2, (kt + 2) % 3);
        const uint32_t so = (uint32_t)st * 20480u;
        #pragma unroll
        for (int ks = 0; ks < 2; ks++) {
            uint32_t afr[4][4], bfr[2][4];
            #pragma unroll
            for (int mt = 0; mt < 4; mt++)
                LDSM4(afr[mt], aAddr + so + (uint32_t)mt*16*80 + ks*32);
            #pragma unroll
            for (int nt2 = 0; nt2 < 2; nt2++)
                LDSM4(bfr[nt2], bAddr + so + (uint32_t)nt2*16*80 + ks*32);
            #pragma unroll
            for (int mt = 0; mt < 4; mt++)
                #pragma unroll
                for (int nt = 0; nt < 4; nt++)
                    MMAF16(acc[mt][nt], afr[mt],
                           bfr[nt >> 1][nt & 1], bfr[nt >> 1][2 + (nt & 1)]);
        }
    }
    CP_WAIT0();

    const int crow = lane >> 2, ccol = (lane & 3) * 2;
    if (mode == 0) {
        #pragma unroll
        for (int nt = 0; nt < 4; nt++) {
            const int n = (int)n0 + wn*32 + nt*8 + ccol;
            const float b0v = bias[n], b1v = bias[n + 1];
            #pragma unroll
            for (int mt = 0; mt < 4; mt++) {
                const size_t m = m0 + wm*64 + mt*16 + crow;
                float2 v0, v1;
                v0.x = acc[mt][nt][0] + b0v; v0.y = acc[mt][nt][1] + b1v;
                v1.x = acc[mt][nt][2] + b0v; v1.y = acc[mt][nt][3] + b1v;
                *(float2*)(C + m * 1024 + n)       = v0;
                *(float2*)(C + (m + 8) * 1024 + n) = v1;
            }
        }
    } else {
        #pragma unroll
        for (int nt = 0; nt < 4; nt++) {
            const int n = (int)n0 + wn*32 + nt*8 + ccol;
            const float b0v = bias[n], b1v = bias[n + 1];
            const int h = n >> 6, e = n & 63;
            #pragma unroll
            for (int mt = 0; mt < 4; mt++) {
                #pragma unroll
                for (int half = 0; half < 2; half++) {
                    const size_t m = m0 + wm*64 + mt*16 + crow + half*8;
                    const int b2 = (int)(m >> 10), s = (int)(m & 1023);
                    const size_t o = (((size_t)(b2*16 + h) * 1024 + s) * 64 + e);
                    const float v0 = acc[mt][nt][half*2]     + b0v;
                    const float v1 = acc[mt][nt][half*2 + 1] + b1v;
                    const __half h0 = __float2half_rn(v0);
                    const __half h1 = __float2half_rn(v1);
                    *(__half2*)(Oh + o) = __half2(h0, h1);
                    if (mode == 1) {
                        const __half l0 = __float2half_rn(v0 - __half2float(h0));
                        const __half l1 = __float2half_rn(v1 - __half2float(h1));
                        *(__half2*)(Ol + o) = __half2(l0, l1);
                    }
                }
            }
        }
    }
    #undef LOADST
}

// ---------------- V fp32 -> transposed per-head fp16 hi --------------------
__global__ void cvt_vt_kernel()
{
    __shared__ float t[32][33];
    const int bh = blockIdx.z;
    const int b = bh >> 4, h = bh & 15;
    const int s0 = blockIdx.y * 32, e0 = blockIdx.x * 32;
    const int tx = threadIdx.x, ty = threadIdx.y;
    #pragma unroll
    for (int i = 0; i < 4; i++)
        t[ty + i*8][tx] = g_V[((size_t)(b*1024) + s0 + ty + i*8) * 1024 + h*64 + e0 + tx];
    __syncthreads();
    #pragma unroll
    for (int i = 0; i < 4; i++) {
        const float v = t[tx][ty + i*8];
        g_Vth[((size_t)bh * 64 + e0 + ty + i*8) * 1024 + s0 + tx] = __float2half_rn(v);
    }
}

// ---------------- scores via mma (fp16 x2), quirks fused -------------------
// grid (kt, qt, bh), block 128 (4 warps, 2x2 of 32x32)
__global__ __launch_bounds__(128) void scores_mma_kernel()
{
    const int kt = blockIdx.x, qt = blockIdx.y;
    if (kt > qt) return;
    const int bh = blockIdx.z;

    __shared__ __align__(16) char sm[3 * 64 * 144];
    const uint32_t sQH = smem_u32(sm);
    const uint32_t sQL = sQH +  9216;
    const uint32_t sKH = sQH + 18432;

    const int tid = threadIdx.x;
    const int lane = tid & 31, wid = tid >> 5;
    const int wm = wid >> 1, wn = wid & 1;

    const __half* gQH = g_Qh + ((size_t)bh * 1024 + qt*64) * 64;
    const __half* gQL = g_Ql + ((size_t)bh * 1024 + qt*64) * 64;
    const __half* gKH = g_Kh + ((size_t)bh * 1024 + kt*64) * 64;
    #pragma unroll
    for (int i = tid; i < 512; i += 128) {
        const int r = i >> 3, c = i & 7;
        const size_t go = (size_t)r * 64 + c * 8;
        const uint32_t so = r * 144 + c * 16;
        *(uint4*)(sm + so)         = *(const uint4*)(gQH + go);
        *(uint4*)(sm + 9216 + so)  = *(const uint4*)(gQL + go);
        *(uint4*)(sm + 18432 + so) = *(const uint4*)(gKH + go);
    }
    __syncthreads();

    float acc[2][4][4];
    #pragma unroll
    for (int a = 0; a < 2; a++)
        #pragma unroll
        for (int b2 = 0; b2 < 4; b2++)
            #pragma unroll
            for (int c = 0; c < 4; c++) acc[a][b2][c] = 0.f;

    const uint32_t aOff = (uint32_t)(wm*32 + (lane & 15)) * 144 + ((lane >> 4) << 4);
    const uint32_t bOff = (uint32_t)(wn*32 + ((lane >> 3) & 1)*8 + (lane & 7)) * 144 + ((lane >> 4) << 4);

    #pragma unroll
    for (int es = 0; es < 4; es++) {
        const uint32_t cb = es * 32;
        uint32_t ah[2][4], al[2][4], bh2[2][4];
        #pragma unroll
        for (int mt = 0; mt < 2; mt++) {
            LDSM4(ah[mt], sQH + aOff + (uint32_t)mt*16*144 + cb);
            LDSM4(al[mt], sQL + aOff + (uint32_t)mt*16*144 + cb);
        }
        #pragma unroll
        for (int nt2 = 0; nt2 < 2; nt2++)
            LDSM4(bh2[nt2], sKH + bOff + (uint32_t)nt2*16*144 + cb);
        #pragma unroll
        for (int mt = 0; mt < 2; mt++)
            #pragma unroll
            for (int nt = 0; nt < 4; nt++) {
                MMAF16(acc[mt][nt], ah[mt], bh2[nt>>1][nt&1], bh2[nt>>1][2+(nt&1)]);
                MMAF16(acc[mt][nt], al[mt], bh2[nt>>1][nt&1], bh2[nt>>1][2+(nt&1)]);
            }
    }

    const float scale = 0.35355339059327373f;  // 1/sqrt(8) batch-size quirk
    float* out = g_Sc + (size_t)bh * S_ * S_;
    #pragma unroll
    for (int mt = 0; mt < 2; mt++) {
        #pragma unroll
        for (int half = 0; half < 2; half++) {
            const int q = qt*64 + wm*32 + mt*16 + (lane >> 2) + half*8;
            #pragma unroll
            for (int nt = 0; nt < 4; nt++) {
                const int k0 = kt*64 + wn*32 + nt*8 + (lane & 3)*2;
                float v0 = acc[mt][nt][half*2]     * scale;
                float v1 = acc[mt][nt][half*2 + 1] * scale;
                if (k0     > q || v0 == 0.0f) v0 = -1e9f;
                if (k0 + 1 > q || v1 == 0.0f) v1 = -1e9f;
                *(float2*)(out + (size_t)q * S_ + k0) = make_float2(v0, v1);
            }
        }
    }
}

// ---------------- softmax over heads -> fp16 attn (hi only) ----------------
__global__ void softmax_h_kernel()
{
    const int k = blockIdx.x * 256 + threadIdx.x;
    const int q = blockIdx.y;
    const int b = blockIdx.z;
    const int kmax = ((q >> 6) + 1) << 6;
    if (k >= kmax) return;

    const size_t base = (size_t)b * H_ * S_ * S_ + (size_t)q * S_ + k;
    const size_t hs   = (size_t)S_ * S_;
    float s[H_];
    float m = -3.4e38f;
    #pragma unroll
    for (int h = 0; h < H_; h++) { s[h] = g_Sc[base + h * hs]; m = fmaxf(m, s[h]); }
    float Z = 0.f;
    #pragma unroll
    for (int h = 0; h < H_; h++) { s[h] = expf(s[h] - m); Z += s[h]; }
    const float inv = 1.0f / Z;
    #pragma unroll
    for (int h = 0; h < H_; h++)
        g_Ah[base + h * hs] = __float2half_rn(s[h] * inv);
}

// ---------------- V tile sums + prefix scan --------------------------------
__global__ void tilesum_kernel()
{
    const int blk = blockIdx.x;
    const int e = threadIdx.x;
    const int tt = blk & (NT_ - 1);
    const int bh = blk / NT_;
    const int b = bh >> 4, h = bh & 15;
    const float* Vb = g_V + ((size_t)(b*S_ + tt*64)) * HE_ + h*64 + e;
    float sum = 0.f;
    #pragma unroll 8
    for (int k = 0; k < 64; k++) sum += Vb[(size_t)k * HE_];
    g_TS[((size_t)bh * NT_ + tt) * E_ + e] = sum;
}

__global__ void scan_kernel()
{
    const int id = blockIdx.x * 256 + threadIdx.x;
    const int e = id & 63, bh = id >> 6;
    float* P = g_P + (size_t)bh * (NT_ + 1) * E_;
    float p = 0.f;
    P[e] = 0.f;
    #pragma unroll
    for (int tt = 0; tt < NT_; tt++) {
        p += g_TS[((size_t)bh * NT_ + tt) * E_ + e];
        P[(tt + 1) * E_ + e] = p;
    }
}

// ---------------- attn @ V via mma (attn hi only) + masked suffix ----------
// grid (qt, bh), block 128; epilogue writes PACKED fold-2048 AO operand
__global__ __launch_bounds__(128) void attnv_mma_kernel()
{
    const int qt = blockIdx.x, bh = blockIdx.y;
    const int b = bh >> 4, h = bh & 15;

    __shared__ __align__(16) char sm[2 * 64 * 144];
    const uint32_t sAH = smem_u32(sm);
    const uint32_t sVH = sAH + 9216;

    const int tid = threadIdx.x;
    const int lane = tid & 31, wid = tid >> 5;
    const int wm = wid >> 1, wn = wid & 1;

    float acc[2][4][4];
    #pragma unroll
    for (int a = 0; a < 2; a++)
        #pragma unroll
        for (int b2 = 0; b2 < 4; b2++)
            #pragma unroll
            for (int c = 0; c < 4; c++) acc[a][b2][c] = 0.f;

    const uint32_t aOff = (uint32_t)(wm*32 + (lane & 15)) * 144 + ((lane >> 4) << 4);
    const uint32_t bOff = (uint32_t)(wn*32 + ((lane >> 3) & 1)*8 + (lane & 7)) * 144 + ((lane >> 4) << 4);

    const __half* gAH0 = g_Ah + ((size_t)bh * 1024 + qt*64) * 1024;
    const __half* gVH0 = g_Vth + (size_t)bh * 64 * 1024;

    for (int kt = 0; kt <= qt; kt++) {
        __syncthreads();
        #pragma unroll
        for (int i = tid; i < 512; i += 128) {
            const int r = i >> 3, c = i & 7;
            const size_t go = (size_t)r * 1024 + kt*64 + c * 8;
            const uint32_t so = r * 144 + c * 16;
            *(uint4*)(sm + so)        = *(const uint4*)(gAH0 + go);
            *(uint4*)(sm + 9216 + so) = *(const uint4*)(gVH0 + go);
        }
        __syncthreads();

        #pragma unroll
        for (int ks = 0; ks < 4; ks++) {
            const uint32_t cb = ks * 32;
            uint32_t ah[2][4], vh[2][4];
            #pragma unroll
            for (int mt = 0; mt < 2; mt++)
                LDSM4(ah[mt], sAH + aOff + (uint32_t)mt*16*144 + cb);
            #pragma unroll
            for (int nt2 = 0; nt2 < 2; nt2++)
                LDSM4(vh[nt2], sVH + bOff + (uint32_t)nt2*16*144 + cb);
            #pragma unroll
            for (int mt = 0; mt < 2; mt++)
                #pragma unroll
                for (int nt = 0; nt < 4; nt++)
                    MMAF16(acc[mt][nt], ah[mt], vh[nt>>1][nt&1], vh[nt>>1][2+(nt&1)]);
        }
    }

    // masked suffix: attn = 1/16 exactly for k beyond causal band; write
    // packed [hi | lo] fold-2048 operand for the output projection GEMM.
    const float* P = g_P + (size_t)bh * (NT_ + 1) * E_;
    #pragma unroll
    for (int nt = 0; nt < 4; nt++) {
        const int e0 = wn*32 + nt*8 + (lane & 3)*2;
        const float s0 = (P[NT_*E_ + e0]     - P[(qt+1)*E_ + e0])     * 0.0625f;
        const float s1 = (P[NT_*E_ + e0 + 1] - P[(qt+1)*E_ + e0 + 1]) * 0.0625f;
        #pragma unroll
        for (int mt = 0; mt < 2; mt++) {
            #pragma unroll
            for (int half = 0; half < 2; half++) {
                const int q = wm*32 + mt*16 + (lane >> 2) + half*8;
                const float v0 = acc[mt][nt][half*2]     + s0;
                const float v1 = acc[mt][nt][half*2 + 1] + s1;
                const __half h0 = __float2half_rn(v0);
                const __half h1 = __float2half_rn(v1);
                const __half l0 = __float2half_rn(v0 - __half2float(h0));
                const __half l1 = __float2half_rn(v1 - __half2float(h1));
                __half* base = g_AOp + ((size_t)(b*1024 + qt*64 + q)) * KP_ + h*64 + e0;
                *(__half2*)(base)        = __half2(h0, h1);
                *(__half2*)(base + 1024) = __half2(l0, l1);
            }
        }
    }
}

// ---------------- launch ---------------------------------------------------
extern "C" void kernel_launch(void* const* d_in, const int* in_sizes, int n_in,
                              void* d_out, int out_size)
{
    const float* X1 = (const float*)d_in[0];
    const float* X2 = (const float*)d_in[1];
    const float* Wq = (const float*)d_in[2];
    const float* bq = (const float*)d_in[3];
    const float* Wk = (const float*)d_in[4];
    const float* bk = (const float*)d_in[5];
    const float* Wv = (const float*)d_in[6];
    const float* bv = (const float*)d_in[7];
    const float* Wo = (const float*)d_in[8];
    const float* bo = (const float*)d_in[9];
    float* out = (float*)d_out;

    void *pV;
    void *pX1p, *pX2p, *pAOp, *pWqp, *pWkp, *pWvp, *pWop;
    void *pQh, *pQl, *pKh;
    cudaGetSymbolAddress(&pV,  g_V);
    cudaGetSymbolAddress(&pX1p, g_X1p); cudaGetSymbolAddress(&pX2p, g_X2p);
    cudaGetSymbolAddress(&pAOp, g_AOp);
    cudaGetSymbolAddress(&pWqp, g_Wqp); cudaGetSymbolAddress(&pWkp, g_Wkp);
    cudaGetSymbolAddress(&pWvp, g_Wvp); cudaGetSymbolAddress(&pWop, g_Wop);
    cudaGetSymbolAddress(&pQh, g_Qh);   cudaGetSymbolAddress(&pQl, g_Ql);
    cudaGetSymbolAddress(&pKh, g_Kh);

    const uint32_t SMEM_G = 61440;
    cudaFuncSetAttribute(gemm_mma_kernel,
                         cudaFuncAttributeMaxDynamicSharedMemorySize, SMEM_G);

    const int n4x = BS_ * D_ / 4;
    pack_x_kernel<<<n4x / 256, 256>>>(X1, (__half*)pX1p, n4x);
    pack_x_kernel<<<n4x / 256, 256>>>(X2, (__half*)pX2p, n4x);

    const dim3 gT(32, 32), bT(32, 8);
    pack_w_kernel<<<gT, bT>>>(Wq, (__half*)pWqp);
    pack_w_kernel<<<gT, bT>>>(Wk, (__half*)pWkp);
    pack_w_kernel<<<gT, bT>>>(Wv, (__half*)pWvp);
    pack_w_kernel<<<gT, bT>>>(Wo, (__half*)pWop);

    const dim3 gG(HE_ / 128, BS_ / 128);
    gemm_mma_kernel<<<gG, 256, SMEM_G>>>((__half*)pX1p, (__half*)pWqp, bq,
                                         nullptr, (__half*)pQh, (__half*)pQl, 1);
    gemm_mma_kernel<<<gG, 256, SMEM_G>>>((__half*)pX2p, (__half*)pWkp, bk,
                                         nullptr, (__half*)pKh, nullptr, 2);
    gemm_mma_kernel<<<gG, 256, SMEM_G>>>((__half*)pX2p, (__half*)pWvp, bv,
                                         (float*)pV, nullptr, nullptr, 0);

    cvt_vt_kernel<<<dim3(2, 32, B_*H_), dim3(32, 8)>>>();
    tilesum_kernel<<<B_ * H_ * NT_, 64>>>();
    scan_kernel<<<(B_ * H_ * E_) / 256, 256>>>();

    scores_mma_kernel<<<dim3(NT_, NT_, B_ * H_), 128>>>();
    softmax_h_kernel<<<dim3(S_ / 256, S_, B_), 256>>>();
    attnv_mma_kernel<<<dim3(NT_, B_ * H_), 128>>>();

    gemm_mma_kernel<<<gG, 256, SMEM_G>>>((__half*)pAOp, (__half*)pWop, bo,
                                         out, nullptr, nullptr, 0);
}

// round 9
// speedup vs baseline: 1.2393x; 1.0309x over previous
#include <cuda_runtime.h>
#include <cuda_fp16.h>
#include <cstdint>
#include <math.h>

#define B_  8
#define S_  1024
#define D_  1024
#define H_  16
#define E_  64
#define HE_ 1024
#define BS_ (B_*S_)
#define NT_ (S_/64)
#define KP_ 2048          // packed K for projections: [Xh | Xl] x [Wh | Wh]

// ---------------- scratch (device globals; no runtime allocation) ----------
__device__ float g_Sc[(size_t)H_*S_*S_];   // per-batch score scratch (L2-resident)
__device__ float g_TS[B_*H_*NT_*E_];
__device__ float g_P [B_*H_*(NT_+1)*E_];

// packed fp16 operands for projection GEMMs (K folded x2)
__device__ __half g_X1p[(size_t)BS_*KP_];
__device__ __half g_X2p[(size_t)BS_*KP_];
__device__ __half g_AOp[(size_t)BS_*KP_];
__device__ __half g_Wqp[(size_t)HE_*KP_];
__device__ __half g_Wkp[(size_t)HE_*KP_];
__device__ __half g_Wvp[(size_t)HE_*KP_];
__device__ __half g_Wop[(size_t)HE_*KP_];

// per-head fp16 operands for attention mma
__device__ __half g_Qh[(size_t)B_*H_*S_*E_];   // [bh][s][e]
__device__ __half g_Kh[(size_t)B_*H_*S_*E_];   // [bh][s][e]
__device__ __half g_Vth[(size_t)B_*H_*E_*S_];  // [bh][e][s]
__device__ __half g_Ah[(size_t)B_*H_*S_*S_];   // [bh][q][k] (hi only)

// ---------------- PTX helpers (baseline sm_80+) -----------------------------
__device__ __forceinline__ uint32_t smem_u32(const void* p) {
    uint32_t a;
    asm("{ .reg .u64 t; cvta.to.shared.u64 t, %1; cvt.u32.u64 %0, t; }" : "=r"(a) : "l"(p));
    return a;
}
__device__ __forceinline__ void cp16(uint32_t s, const void* g) {
    asm volatile("cp.async.cg.shared.global [%0], [%1], 16;" :: "r"(s), "l"(g));
}
#define CP_COMMIT() asm volatile("cp.async.commit_group;" ::: "memory")
#define CP_WAIT1()  asm volatile("cp.async.wait_group 1;" ::: "memory")
#define CP_WAIT0()  asm volatile("cp.async.wait_group 0;" ::: "memory")

#define LDSM4(r, a) \
    asm volatile("ldmatrix.sync.aligned.m8n8.x4.shared.b16 {%0,%1,%2,%3}, [%4];" \
        : "=r"((r)[0]), "=r"((r)[1]), "=r"((r)[2]), "=r"((r)[3]) : "r"(a))

#define MMAF16(c, a, b0v, b1v) \
    asm volatile("mma.sync.aligned.m16n8k16.row.col.f32.f16.f16.f32 " \
        "{%0,%1,%2,%3}, {%4,%5,%6,%7}, {%8,%9}, {%0,%1,%2,%3};" \
        : "+f"((c)[0]), "+f"((c)[1]), "+f"((c)[2]), "+f"((c)[3]) \
        : "r"((a)[0]), "r"((a)[1]), "r"((a)[2]), "r"((a)[3]), "r"(b0v), "r"(b1v))

// ---------------- pack kernels ---------------------------------------------
__global__ __launch_bounds__(256) void pack_x_kernel(
    const float* __restrict__ in, __half* __restrict__ out, int n4)
{
    int i = blockIdx.x * 256 + threadIdx.x;
    if (i >= n4) return;
    const int row = i >> 8;
    const int c   = (i & 255) * 4;
    float4 v = ((const float4*)in)[i];
    float f[4] = {v.x, v.y, v.z, v.w};
    __half hh[4], ll[4];
    #pragma unroll
    for (int j = 0; j < 4; j++) {
        hh[j] = __float2half_rn(f[j]);
        ll[j] = __float2half_rn(f[j] - __half2float(hh[j]));
    }
    __half* base = out + (size_t)row * KP_;
    *(__half2*)(base + c)          = __half2(hh[0], hh[1]);
    *(__half2*)(base + c + 2)      = __half2(hh[2], hh[3]);
    *(__half2*)(base + 1024 + c)   = __half2(ll[0], ll[1]);
    *(__half2*)(base + 1024 + c+2) = __half2(ll[2], ll[3]);
}

__global__ __launch_bounds__(256) void pack_w_kernel(
    const float* __restrict__ W, __half* __restrict__ out)
{
    __shared__ float t[32][33];
    const int n0 = blockIdx.x * 32, k0 = blockIdx.y * 32;
    const int tx = threadIdx.x, ty = threadIdx.y;
    #pragma unroll
    for (int i = 0; i < 4; i++)
        t[ty + i*8][tx] = W[(size_t)(k0 + ty + i*8) * 1024 + n0 + tx];
    __syncthreads();
    #pragma unroll
    for (int i = 0; i < 4; i++) {
        float v = t[tx][ty + i*8];
        __half h = __float2half_rn(v);
        size_t o = (size_t)(n0 + ty + i*8) * KP_ + k0 + tx;
        out[o]        = h;
        out[o + 1024] = h;
    }
}

// ---------------- projection GEMM (mma.sync fp16, K-fold x2) ---------------
// modes: 0 = fp32 C row-major; 2 = per-head fp16 hi; 3 = per-head fp16 TRANSPOSED [bh][e][s]
__global__ __launch_bounds__(256) void gemm_mma_kernel(
    const __half* __restrict__ Ap, const __half* __restrict__ Bp,
    const float* __restrict__ bias, float* __restrict__ C,
    __half* __restrict__ Oh, int mode)
{
    extern __shared__ char smch[];
    const uint32_t sb = smem_u32(smch);
    const int tid = threadIdx.x;
    const int lane = tid & 31, wid = tid >> 5;
    const int wm = wid >> 2, wn = wid & 3;
    const size_t m0 = (size_t)blockIdx.y * 128;
    const size_t n0 = (size_t)blockIdx.x * 128;

    const int lr = tid >> 2;
    const int lco = (tid & 3) * 16;
    const __half* gA0 = Ap + (m0 + lr) * KP_ + (tid & 3) * 8;
    const __half* gB0 = Bp + (n0 + lr) * KP_ + (tid & 3) * 8;
    const uint32_t smA = sb + lr * 80 + lco;
    const uint32_t smB = smA + 10240;

    float acc[4][4][4];
    #pragma unroll
    for (int a = 0; a < 4; a++)
        #pragma unroll
        for (int b = 0; b < 4; b++)
            #pragma unroll
            for (int c = 0; c < 4; c++) acc[a][b][c] = 0.f;

    #define LOADST(kt, st) do {                                        \
        const uint32_t so_ = (uint32_t)(st) * 20480u;                  \
        const __half* ga_ = gA0 + (kt) * 32;                           \
        const __half* gb_ = gB0 + (kt) * 32;                           \
        cp16(smA + so_,           ga_);                                \
        cp16(smA + so_ + 64*80,   ga_ + (size_t)64 * KP_);             \
        cp16(smB + so_,           gb_);                                \
        cp16(smB + so_ + 64*80,   gb_ + (size_t)64 * KP_);             \
        CP_COMMIT();                                                   \
    } while (0)

    LOADST(0, 0);
    LOADST(1, 1);

    const uint32_t aAddr = sb + (uint32_t)(wm*64 + (lane & 15)) * 80 + ((lane >> 4) << 4);
    const uint32_t bAddr = sb + 10240 +
        (uint32_t)(wn*32 + ((lane >> 3) & 1) * 8 + (lane & 7)) * 80 + ((lane >> 4) << 4);

    const int NKT = KP_ / 32;   // 64
    #pragma unroll 1
    for (int kt = 0; kt < NKT; kt++) {
        const int st = kt % 3;
        CP_WAIT1();
        __syncthreads();
        if (kt + 2 < NKT) LOADST(kt + 2, (kt + 2) % 3);
        const uint32_t so = (uint32_t)st * 20480u;
        #pragma unroll
        for (int ks = 0; ks < 2; ks++) {
            uint32_t afr[4][4], bfr[2][4];
            #pragma unroll
            for (int mt = 0; mt < 4; mt++)
                LDSM4(afr[mt], aAddr + so + (uint32_t)mt*16*80 + ks*32);
            #pragma unroll
            for (int nt2 = 0; nt2 < 2; nt2++)
                LDSM4(bfr[nt2], bAddr + so + (uint32_t)nt2*16*80 + ks*32);
            #pragma unroll
            for (int mt = 0; mt < 4; mt++)
                #pragma unroll
                for (int nt = 0; nt < 4; nt++)
                    MMAF16(acc[mt][nt], afr[mt],
                           bfr[nt >> 1][nt & 1], bfr[nt >> 1][2 + (nt & 1)]);
        }
    }
    CP_WAIT0();

    const int crow = lane >> 2, ccol = (lane & 3) * 2;
    if (mode == 0) {
        #pragma unroll
        for (int nt = 0; nt < 4; nt++) {
            const int n = (int)n0 + wn*32 + nt*8 + ccol;
            const float b0v = bias[n], b1v = bias[n + 1];
            #pragma unroll
            for (int mt = 0; mt < 4; mt++) {
                const size_t m = m0 + wm*64 + mt*16 + crow;
                float2 v0, v1;
                v0.x = acc[mt][nt][0] + b0v; v0.y = acc[mt][nt][1] + b1v;
                v1.x = acc[mt][nt][2] + b0v; v1.y = acc[mt][nt][3] + b1v;
                *(float2*)(C + m * 1024 + n)       = v0;
                *(float2*)(C + (m + 8) * 1024 + n) = v1;
            }
        }
    } else if (mode == 2) {
        #pragma unroll
        for (int nt = 0; nt < 4; nt++) {
            const int n = (int)n0 + wn*32 + nt*8 + ccol;
            const float b0v = bias[n], b1v = bias[n + 1];
            const int h = n >> 6, e = n & 63;
            #pragma unroll
            for (int mt = 0; mt < 4; mt++) {
                #pragma unroll
                for (int half = 0; half < 2; half++) {
                    const size_t m = m0 + wm*64 + mt*16 + crow + half*8;
                    const int b2 = (int)(m >> 10), s = (int)(m & 1023);
                    const size_t o = (((size_t)(b2*16 + h) * 1024 + s) * 64 + e);
                    *(__half2*)(Oh + o) = __half2(
                        __float2half_rn(acc[mt][nt][half*2]     + b0v),
                        __float2half_rn(acc[mt][nt][half*2 + 1] + b1v));
                }
            }
        }
    } else {   // mode 3: transposed per-head [bh][e][s]
        #pragma unroll
        for (int nt = 0; nt < 4; nt++) {
            const int n = (int)n0 + wn*32 + nt*8 + ccol;
            const float b0v = bias[n], b1v = bias[n + 1];
            const int h = n >> 6, e = n & 63;
            #pragma unroll
            for (int mt = 0; mt < 4; mt++) {
                #pragma unroll
                for (int half = 0; half < 2; half++) {
                    const size_t m = m0 + wm*64 + mt*16 + crow + half*8;
                    const int b2 = (int)(m >> 10), s = (int)(m & 1023);
                    const size_t o0 = (((size_t)(b2*16 + h) * 64 + e)     << 10) + s;
                    const size_t o1 = (((size_t)(b2*16 + h) * 64 + e + 1) << 10) + s;
                    Oh[o0] = __float2half_rn(acc[mt][nt][half*2]     + b0v);
                    Oh[o1] = __float2half_rn(acc[mt][nt][half*2 + 1] + b1v);
                }
            }
        }
    }
    #undef LOADST
}

// ---------------- scores via mma (hi-only), quirks fused, per-batch --------
// grid (kt, qt, h), block 128 (4 warps, 2x2 of 32x32); writes per-b scratch g_Sc
__global__ __launch_bounds__(128) void scores_mma_kernel(int b)
{
    const int kt = blockIdx.x, qt = blockIdx.y;
    if (kt > qt) return;
    const int h = blockIdx.z;
    const int bh = b * 16 + h;

    __shared__ __align__(16) char sm[2 * 64 * 144];
    const uint32_t sQH = smem_u32(sm);
    const uint32_t sKH = sQH + 9216;

    const int tid = threadIdx.x;
    const int lane = tid & 31, wid = tid >> 5;
    const int wm = wid >> 1, wn = wid & 1;

    const __half* gQH = g_Qh + ((size_t)bh * 1024 + qt*64) * 64;
    const __half* gKH = g_Kh + ((size_t)bh * 1024 + kt*64) * 64;
    #pragma unroll
    for (int i = tid; i < 512; i += 128) {
        const int r = i >> 3, c = i & 7;
        const size_t go = (size_t)r * 64 + c * 8;
        const uint32_t so = r * 144 + c * 16;
        *(uint4*)(sm + so)        = *(const uint4*)(gQH + go);
        *(uint4*)(sm + 9216 + so) = *(const uint4*)(gKH + go);
    }
    __syncthreads();

    float acc[2][4][4];
    #pragma unroll
    for (int a = 0; a < 2; a++)
        #pragma unroll
        for (int b2 = 0; b2 < 4; b2++)
            #pragma unroll
            for (int c = 0; c < 4; c++) acc[a][b2][c] = 0.f;

    const uint32_t aOff = (uint32_t)(wm*32 + (lane & 15)) * 144 + ((lane >> 4) << 4);
    const uint32_t bOff = (uint32_t)(wn*32 + ((lane >> 3) & 1)*8 + (lane & 7)) * 144 + ((lane >> 4) << 4);

    #pragma unroll
    for (int es = 0; es < 4; es++) {
        const uint32_t cb = es * 32;
        uint32_t ah[2][4], bh2[2][4];
        #pragma unroll
        for (int mt = 0; mt < 2; mt++)
            LDSM4(ah[mt], sQH + aOff + (uint32_t)mt*16*144 + cb);
        #pragma unroll
        for (int nt2 = 0; nt2 < 2; nt2++)
            LDSM4(bh2[nt2], sKH + bOff + (uint32_t)nt2*16*144 + cb);
        #pragma unroll
        for (int mt = 0; mt < 2; mt++)
            #pragma unroll
            for (int nt = 0; nt < 4; nt++)
                MMAF16(acc[mt][nt], ah[mt], bh2[nt>>1][nt&1], bh2[nt>>1][2+(nt&1)]);
    }

    const float scale = 0.35355339059327373f;  // 1/sqrt(8) batch-size quirk
    float* out = g_Sc + (size_t)h * S_ * S_;
    #pragma unroll
    for (int mt = 0; mt < 2; mt++) {
        #pragma unroll
        for (int half = 0; half < 2; half++) {
            const int q = qt*64 + wm*32 + mt*16 + (lane >> 2) + half*8;
            #pragma unroll
            for (int nt = 0; nt < 4; nt++) {
                const int k0 = kt*64 + wn*32 + nt*8 + (lane & 3)*2;
                float v0 = acc[mt][nt][half*2]     * scale;
                float v1 = acc[mt][nt][half*2 + 1] * scale;
                if (k0     > q || v0 == 0.0f) v0 = -1e9f;
                if (k0 + 1 > q || v1 == 0.0f) v1 = -1e9f;
                *(float2*)(out + (size_t)q * S_ + k0) = make_float2(v0, v1);
            }
        }
    }
}

// ---------------- softmax over heads -> fp16 attn (hi only), per-batch -----
__global__ void softmax_h_kernel(int b)
{
    const int k = blockIdx.x * 256 + threadIdx.x;
    const int q = blockIdx.y;
    const int kmax = ((q >> 6) + 1) << 6;
    if (k >= kmax) return;

    const size_t so = (size_t)q * S_ + k;
    const size_t hs = (size_t)S_ * S_;
    float s[H_];
    float m = -3.4e38f;
    #pragma unroll
    for (int h = 0; h < H_; h++) { s[h] = g_Sc[so + h * hs]; m = fmaxf(m, s[h]); }
    float Z = 0.f;
    #pragma unroll
    for (int h = 0; h < H_; h++) { s[h] = expf(s[h] - m); Z += s[h]; }
    const float inv = 1.0f / Z;
    const size_t ab = (size_t)b * H_ * S_ * S_ + so;
    #pragma unroll
    for (int h = 0; h < H_; h++)
        g_Ah[ab + h * hs] = __float2half_rn(s[h] * inv);
}

// ---------------- V tile sums (from transposed fp16 V) + prefix scan -------
__global__ void tilesum_kernel()
{
    const int blk = blockIdx.x;
    const int e = threadIdx.x;
    const int tt = blk & (NT_ - 1);
    const int bh = blk / NT_;
    const __half2* Vb = (const __half2*)(g_Vth + (((size_t)bh * 64 + e) << 10) + tt*64);
    float sum = 0.f;
    #pragma unroll
    for (int k = 0; k < 32; k++) {
        const __half2 v = Vb[k];
        sum += __half2float(v.x) + __half2float(v.y);
    }
    g_TS[((size_t)bh * NT_ + tt) * E_ + e] = sum;
}

__global__ void scan_kernel()
{
    const int id = blockIdx.x * 256 + threadIdx.x;
    const int e = id & 63, bh = id >> 6;
    float* P = g_P + (size_t)bh * (NT_ + 1) * E_;
    float p = 0.f;
    P[e] = 0.f;
    #pragma unroll
    for (int tt = 0; tt < NT_; tt++) {
        p += g_TS[((size_t)bh * NT_ + tt) * E_ + e];
        P[(tt + 1) * E_ + e] = p;
    }
}

// ---------------- attn @ V via mma (attn hi only) + masked suffix ----------
// grid (qt, bh), block 128; epilogue writes PACKED fold-2048 AO operand
__global__ __launch_bounds__(128) void attnv_mma_kernel()
{
    const int qt = blockIdx.x, bh = blockIdx.y;
    const int b = bh >> 4, h = bh & 15;

    __shared__ __align__(16) char sm[2 * 64 * 144];
    const uint32_t sAH = smem_u32(sm);
    const uint32_t sVH = sAH + 9216;

    const int tid = threadIdx.x;
    const int lane = tid & 31, wid = tid >> 5;
    const int wm = wid >> 1, wn = wid & 1;

    float acc[2][4][4];
    #pragma unroll
    for (int a = 0; a < 2; a++)
        #pragma unroll
        for (int b2 = 0; b2 < 4; b2++)
            #pragma unroll
            for (int c = 0; c < 4; c++) acc[a][b2][c] = 0.f;

    const uint32_t aOff = (uint32_t)(wm*32 + (lane & 15)) * 144 + ((lane >> 4) << 4);
    const uint32_t bOff = (uint32_t)(wn*32 + ((lane >> 3) & 1)*8 + (lane & 7)) * 144 + ((lane >> 4) << 4);

    const __half* gAH0 = g_Ah + ((size_t)bh * 1024 + qt*64) * 1024;
    const __half* gVH0 = g_Vth + (size_t)bh * 64 * 1024;

    for (int kt = 0; kt <= qt; kt++) {
        __syncthreads();
        #pragma unroll
        for (int i = tid; i < 512; i += 128) {
            const int r = i >> 3, c = i & 7;
            const size_t go = (size_t)r * 1024 + kt*64 + c * 8;
            const uint32_t so = r * 144 + c * 16;
            *(uint4*)(sm + so)        = *(const uint4*)(gAH0 + go);
            *(uint4*)(sm + 9216 + so) = *(const uint4*)(gVH0 + go);
        }
        __syncthreads();

        #pragma unroll
        for (int ks = 0; ks < 4; ks++) {
            const uint32_t cb = ks * 32;
            uint32_t ah[2][4], vh[2][4];
            #pragma unroll
            for (int mt = 0; mt < 2; mt++)
                LDSM4(ah[mt], sAH + aOff + (uint32_t)mt*16*144 + cb);
            #pragma unroll
            for (int nt2 = 0; nt2 < 2; nt2++)
                LDSM4(vh[nt2], sVH + bOff + (uint32_t)nt2*16*144 + cb);
            #pragma unroll
            for (int mt = 0; mt < 2; mt++)
                #pragma unroll
                for (int nt = 0; nt < 4; nt++)
                    MMAF16(acc[mt][nt], ah[mt], vh[nt>>1][nt&1], vh[nt>>1][2+(nt&1)]);
        }
    }

    const float* P = g_P + (size_t)bh * (NT_ + 1) * E_;
    #pragma unroll
    for (int nt = 0; nt < 4; nt++) {
        const int e0 = wn*32 + nt*8 + (lane & 3)*2;
        const float s0 = (P[NT_*E_ + e0]     - P[(qt+1)*E_ + e0])     * 0.0625f;
        const float s1 = (P[NT_*E_ + e0 + 1] - P[(qt+1)*E_ + e0 + 1]) * 0.0625f;
        #pragma unroll
        for (int mt = 0; mt < 2; mt++) {
            #pragma unroll
            for (int half = 0; half < 2; half++) {
                const int q = wm*32 + mt*16 + (lane >> 2) + half*8;
                const float v0 = acc[mt][nt][half*2]     + s0;
                const float v1 = acc[mt][nt][half*2 + 1] + s1;
                const __half h0 = __float2half_rn(v0);
                const __half h1 = __float2half_rn(v1);
                const __half l0 = __float2half_rn(v0 - __half2float(h0));
                const __half l1 = __float2half_rn(v1 - __half2float(h1));
                __half* base = g_AOp + ((size_t)(b*1024 + qt*64 + q)) * KP_ + h*64 + e0;
                *(__half2*)(base)        = __half2(h0, h1);
                *(__half2*)(base + 1024) = __half2(l0, l1);
            }
        }
    }
}

// ---------------- launch ---------------------------------------------------
extern "C" void kernel_launch(void* const* d_in, const int* in_sizes, int n_in,
                              void* d_out, int out_size)
{
    const float* X1 = (const float*)d_in[0];
    const float* X2 = (const float*)d_in[1];
    const float* Wq = (const float*)d_in[2];
    const float* bq = (const float*)d_in[3];
    const float* Wk = (const float*)d_in[4];
    const float* bk = (const float*)d_in[5];
    const float* Wv = (const float*)d_in[6];
    const float* bv = (const float*)d_in[7];
    const float* Wo = (const float*)d_in[8];
    const float* bo = (const float*)d_in[9];
    float* out = (float*)d_out;

    void *pX1p, *pX2p, *pAOp, *pWqp, *pWkp, *pWvp, *pWop;
    void *pQh, *pKh, *pVth;
    cudaGetSymbolAddress(&pX1p, g_X1p); cudaGetSymbolAddress(&pX2p, g_X2p);
    cudaGetSymbolAddress(&pAOp, g_AOp);
    cudaGetSymbolAddress(&pWqp, g_Wqp); cudaGetSymbolAddress(&pWkp, g_Wkp);
    cudaGetSymbolAddress(&pWvp, g_Wvp); cudaGetSymbolAddress(&pWop, g_Wop);
    cudaGetSymbolAddress(&pQh, g_Qh);   cudaGetSymbolAddress(&pKh, g_Kh);
    cudaGetSymbolAddress(&pVth, g_Vth);

    const uint32_t SMEM_G = 61440;
    cudaFuncSetAttribute(gemm_mma_kernel,
                         cudaFuncAttributeMaxDynamicSharedMemorySize, SMEM_G);

    const int n4x = BS_ * D_ / 4;
    pack_x_kernel<<<n4x / 256, 256>>>(X1, (__half*)pX1p, n4x);
    pack_x_kernel<<<n4x / 256, 256>>>(X2, (__half*)pX2p, n4x);

    const dim3 gT(32, 32), bT(32, 8);
    pack_w_kernel<<<gT, bT>>>(Wq, (__half*)pWqp);
    pack_w_kernel<<<gT, bT>>>(Wk, (__half*)pWkp);
    pack_w_kernel<<<gT, bT>>>(Wv, (__half*)pWvp);
    pack_w_kernel<<<gT, bT>>>(Wo, (__half*)pWop);

    const dim3 gG(HE_ / 128, BS_ / 128);
    // Q projection -> per-head fp16 hi
    gemm_mma_kernel<<<gG, 256, SMEM_G>>>((__half*)pX1p, (__half*)pWqp, bq,
                                         nullptr, (__half*)pQh, 2);
    // K projection -> per-head fp16 hi
    gemm_mma_kernel<<<gG, 256, SMEM_G>>>((__half*)pX2p, (__half*)pWkp, bk,
                                         nullptr, (__half*)pKh, 2);
    // V projection -> transposed per-head fp16 directly
    gemm_mma_kernel<<<gG, 256, SMEM_G>>>((__half*)pX2p, (__half*)pWvp, bv,
                                         nullptr, (__half*)pVth, 3);

    tilesum_kernel<<<B_ * H_ * NT_, 64>>>();
    scan_kernel<<<(B_ * H_ * E_) / 256, 256>>>();

    // per-batch scores -> softmax on a shared L2-resident scratch
    for (int b = 0; b < B_; b++) {
        scores_mma_kernel<<<dim3(NT_, NT_, H_), 128>>>(b);
        softmax_h_kernel<<<dim3(S_ / 256, S_, 1), 256>>>(b);
    }

    attnv_mma_kernel<<<dim3(NT_, B_ * H_), 128>>>();

    gemm_mma_kernel<<<gG, 256, SMEM_G>>>((__half*)pAOp, (__half*)pWop, bo,
                                         out, nullptr, 0);
}

// round 10
// speedup vs baseline: 1.5949x; 1.2869x over previous
#include <cuda_runtime.h>
#include <cuda_fp16.h>
#include <cstdint>
#include <math.h>

#define B_  8
#define S_  1024
#define D_  1024
#define H_  16
#define E_  64
#define HE_ 1024
#define BS_ (B_*S_)
#define NT_ (S_/64)
#define KPO_ 2048         // fold-2048 only for the output projection

// ---------------- scratch (device globals; no runtime allocation) ----------
__device__ float g_Sc[(size_t)H_*S_*S_];   // per-batch score scratch (L2-resident)
__device__ float g_TS[B_*H_*NT_*E_];
__device__ float g_P [B_*H_*(NT_+1)*E_];

// fp16 operands
__device__ __half g_X1h[(size_t)BS_*D_];       // plain hi
__device__ __half g_X2h[(size_t)BS_*D_];
__device__ __half g_AOp[(size_t)BS_*KPO_];     // folded [hi | lo]
__device__ __half g_Wq [(size_t)HE_*D_];       // [N,K] K-major, single copy
__device__ __half g_Wk [(size_t)HE_*D_];
__device__ __half g_Wv [(size_t)HE_*D_];
__device__ __half g_Wop[(size_t)HE_*KPO_];     // [N, 2048] duplicated hi

// per-head fp16 operands for attention mma
__device__ __half g_Qh[(size_t)B_*H_*S_*E_];   // [bh][s][e]
__device__ __half g_Kh[(size_t)B_*H_*S_*E_];   // [bh][s][e]
__device__ __half g_Vth[(size_t)B_*H_*E_*S_];  // [bh][e][s]
__device__ __half g_Ah[(size_t)B_*H_*S_*S_];   // [bh][q][k] (hi only)

// ---------------- PTX helpers (baseline sm_80+) -----------------------------
__device__ __forceinline__ uint32_t smem_u32(const void* p) {
    uint32_t a;
    asm("{ .reg .u64 t; cvta.to.shared.u64 t, %1; cvt.u32.u64 %0, t; }" : "=r"(a) : "l"(p));
    return a;
}
__device__ __forceinline__ void cp16(uint32_t s, const void* g) {
    asm volatile("cp.async.cg.shared.global [%0], [%1], 16;" :: "r"(s), "l"(g));
}
#define CP_COMMIT() asm volatile("cp.async.commit_group;" ::: "memory")
#define CP_WAIT1()  asm volatile("cp.async.wait_group 1;" ::: "memory")
#define CP_WAIT0()  asm volatile("cp.async.wait_group 0;" ::: "memory")

#define LDSM4(r, a) \
    asm volatile("ldmatrix.sync.aligned.m8n8.x4.shared.b16 {%0,%1,%2,%3}, [%4];" \
        : "=r"((r)[0]), "=r"((r)[1]), "=r"((r)[2]), "=r"((r)[3]) : "r"(a))

#define MMAF16(c, a, b0v, b1v) \
    asm volatile("mma.sync.aligned.m16n8k16.row.col.f32.f16.f16.f32 " \
        "{%0,%1,%2,%3}, {%4,%5,%6,%7}, {%8,%9}, {%0,%1,%2,%3};" \
        : "+f"((c)[0]), "+f"((c)[1]), "+f"((c)[2]), "+f"((c)[3]) \
        : "r"((a)[0]), "r"((a)[1]), "r"((a)[2]), "r"((a)[3]), "r"(b0v), "r"(b1v))

// ---------------- pack kernels ---------------------------------------------
// plain fp32 -> fp16 convert
__global__ __launch_bounds__(256) void cvt_h_kernel(
    const float* __restrict__ in, __half* __restrict__ out, int n4)
{
    int i = blockIdx.x * 256 + threadIdx.x;
    if (i >= n4) return;
    float4 v = ((const float4*)in)[i];
    __half2 a = __half2(__float2half_rn(v.x), __float2half_rn(v.y));
    __half2 b = __half2(__float2half_rn(v.z), __float2half_rn(v.w));
    *(__half2*)(out + i*4)     = a;
    *(__half2*)(out + i*4 + 2) = b;
}

// W fp32 [K=1024, N=1024] -> Wt fp16 [N, kp] K-major; optional dup at +1024
__global__ __launch_bounds__(256) void pack_w_kernel(
    const float* __restrict__ W, __half* __restrict__ out, int kp, int dup)
{
    __shared__ float t[32][33];
    const int n0 = blockIdx.x * 32, k0 = blockIdx.y * 32;
    const int tx = threadIdx.x, ty = threadIdx.y;
    #pragma unroll
    for (int i = 0; i < 4; i++)
        t[ty + i*8][tx] = W[(size_t)(k0 + ty + i*8) * 1024 + n0 + tx];
    __syncthreads();
    #pragma unroll
    for (int i = 0; i < 4; i++) {
        float v = t[tx][ty + i*8];
        __half h = __float2half_rn(v);
        size_t o = (size_t)(n0 + ty + i*8) * kp + k0 + tx;
        out[o] = h;
        if (dup) out[o + 1024] = h;
    }
}

// ---------------- GEMM (mma.sync fp16), runtime K pitch --------------------
// modes: 0 = fp32 C row-major; 2 = per-head fp16 hi; 3 = per-head fp16 TRANSPOSED [bh][e][s]
__global__ __launch_bounds__(256) void gemm_mma_kernel(
    const __half* __restrict__ Ap, const __half* __restrict__ Bp,
    const float* __restrict__ bias, float* __restrict__ C,
    __half* __restrict__ Oh, int mode, int kp)
{
    extern __shared__ char smch[];
    const uint32_t sb = smem_u32(smch);
    const int tid = threadIdx.x;
    const int lane = tid & 31, wid = tid >> 5;
    const int wm = wid >> 2, wn = wid & 3;
    const size_t m0 = (size_t)blockIdx.y * 128;
    const size_t n0 = (size_t)blockIdx.x * 128;

    const int lr = tid >> 2;
    const int lco = (tid & 3) * 16;
    const __half* gA0 = Ap + (m0 + lr) * kp + (tid & 3) * 8;
    const __half* gB0 = Bp + (n0 + lr) * kp + (tid & 3) * 8;
    const uint32_t smA = sb + lr * 80 + lco;
    const uint32_t smB = smA + 10240;

    float acc[4][4][4];
    #pragma unroll
    for (int a = 0; a < 4; a++)
        #pragma unroll
        for (int b = 0; b < 4; b++)
            #pragma unroll
            for (int c = 0; c < 4; c++) acc[a][b][c] = 0.f;

    #define LOADST(kt, st) do {                                        \
        const uint32_t so_ = (uint32_t)(st) * 20480u;                  \
        const __half* ga_ = gA0 + (size_t)(kt) * 32;                   \
        const __half* gb_ = gB0 + (size_t)(kt) * 32;                   \
        cp16(smA + so_,           ga_);                                \
        cp16(smA + so_ + 64*80,   ga_ + (size_t)64 * kp);              \
        cp16(smB + so_,           gb_);                                \
        cp16(smB + so_ + 64*80,   gb_ + (size_t)64 * kp);              \
        CP_COMMIT();                                                   \
    } while (0)

    LOADST(0, 0);
    LOADST(1, 1);

    const uint32_t aAddr = sb + (uint32_t)(wm*64 + (lane & 15)) * 80 + ((lane >> 4) << 4);
    const uint32_t bAddr = sb + 10240 +
        (uint32_t)(wn*32 + ((lane >> 3) & 1) * 8 + (lane & 7)) * 80 + ((lane >> 4) << 4);

    const int NKT = kp / 32;
    #pragma unroll 1
    for (int kt = 0; kt < NKT; kt++) {
        const int st = kt % 3;
        CP_WAIT1();
        __syncthreads();
        if (kt + 2 < NKT) LOADST(kt + 2, (kt + 2) % 3);
        const uint32_t so = (uint32_t)st * 20480u;
        #pragma unroll
        for (int ks = 0; ks < 2; ks++) {
            uint32_t afr[4][4], bfr[2][4];
            #pragma unroll
            for (int mt = 0; mt < 4; mt++)
                LDSM4(afr[mt], aAddr + so + (uint32_t)mt*16*80 + ks*32);
            #pragma unroll
            for (int nt2 = 0; nt2 < 2; nt2++)
                LDSM4(bfr[nt2], bAddr + so + (uint32_t)nt2*16*80 + ks*32);
            #pragma unroll
            for (int mt = 0; mt < 4; mt++)
                #pragma unroll
                for (int nt = 0; nt < 4; nt++)
                    MMAF16(acc[mt][nt], afr[mt],
                           bfr[nt >> 1][nt & 1], bfr[nt >> 1][2 + (nt & 1)]);
        }
    }
    CP_WAIT0();

    const int crow = lane >> 2, ccol = (lane & 3) * 2;
    if (mode == 0) {
        #pragma unroll
        for (int nt = 0; nt < 4; nt++) {
            const int n = (int)n0 + wn*32 + nt*8 + ccol;
            const float b0v = bias[n], b1v = bias[n + 1];
            #pragma unroll
            for (int mt = 0; mt < 4; mt++) {
                const size_t m = m0 + wm*64 + mt*16 + crow;
                float2 v0, v1;
                v0.x = acc[mt][nt][0] + b0v; v0.y = acc[mt][nt][1] + b1v;
                v1.x = acc[mt][nt][2] + b0v; v1.y = acc[mt][nt][3] + b1v;
                *(float2*)(C + m * 1024 + n)       = v0;
                *(float2*)(C + (m + 8) * 1024 + n) = v1;
            }
        }
    } else if (mode == 2) {
        #pragma unroll
        for (int nt = 0; nt < 4; nt++) {
            const int n = (int)n0 + wn*32 + nt*8 + ccol;
            const float b0v = bias[n], b1v = bias[n + 1];
            const int h = n >> 6, e = n & 63;
            #pragma unroll
            for (int mt = 0; mt < 4; mt++) {
                #pragma unroll
                for (int half = 0; half < 2; half++) {
                    const size_t m = m0 + wm*64 + mt*16 + crow + half*8;
                    const int b2 = (int)(m >> 10), s = (int)(m & 1023);
                    const size_t o = (((size_t)(b2*16 + h) * 1024 + s) * 64 + e);
                    *(__half2*)(Oh + o) = __half2(
                        __float2half_rn(acc[mt][nt][half*2]     + b0v),
                        __float2half_rn(acc[mt][nt][half*2 + 1] + b1v));
                }
            }
        }
    } else {   // mode 3: transposed per-head [bh][e][s]
        #pragma unroll
        for (int nt = 0; nt < 4; nt++) {
            const int n = (int)n0 + wn*32 + nt*8 + ccol;
            const float b0v = bias[n], b1v = bias[n + 1];
            const int h = n >> 6, e = n & 63;
            #pragma unroll
            for (int mt = 0; mt < 4; mt++) {
                #pragma unroll
                for (int half = 0; half < 2; half++) {
                    const size_t m = m0 + wm*64 + mt*16 + crow + half*8;
                    const int b2 = (int)(m >> 10), s = (int)(m & 1023);
                    const size_t o0 = (((size_t)(b2*16 + h) * 64 + e)     << 10) + s;
                    const size_t o1 = (((size_t)(b2*16 + h) * 64 + e + 1) << 10) + s;
                    Oh[o0] = __float2half_rn(acc[mt][nt][half*2]     + b0v);
                    Oh[o1] = __float2half_rn(acc[mt][nt][half*2 + 1] + b1v);
                }
            }
        }
    }
    #undef LOADST
}

// ---------------- scores via mma (hi-only), quirks fused, per-batch --------
__global__ __launch_bounds__(128) void scores_mma_kernel(int b)
{
    const int kt = blockIdx.x, qt = blockIdx.y;
    if (kt > qt) return;
    const int h = blockIdx.z;
    const int bh = b * 16 + h;

    __shared__ __align__(16) char sm[2 * 64 * 144];
    const uint32_t sQH = smem_u32(sm);
    const uint32_t sKH = sQH + 9216;

    const int tid = threadIdx.x;
    const int lane = tid & 31, wid = tid >> 5;
    const int wm = wid >> 1, wn = wid & 1;

    const __half* gQH = g_Qh + ((size_t)bh * 1024 + qt*64) * 64;
    const __half* gKH = g_Kh + ((size_t)bh * 1024 + kt*64) * 64;
    #pragma unroll
    for (int i = tid; i < 512; i += 128) {
        const int r = i >> 3, c = i & 7;
        const size_t go = (size_t)r * 64 + c * 8;
        const uint32_t so = r * 144 + c * 16;
        *(uint4*)(sm + so)        = *(const uint4*)(gQH + go);
        *(uint4*)(sm + 9216 + so) = *(const uint4*)(gKH + go);
    }
    __syncthreads();

    float acc[2][4][4];
    #pragma unroll
    for (int a = 0; a < 2; a++)
        #pragma unroll
        for (int b2 = 0; b2 < 4; b2++)
            #pragma unroll
            for (int c = 0; c < 4; c++) acc[a][b2][c] = 0.f;

    const uint32_t aOff = (uint32_t)(wm*32 + (lane & 15)) * 144 + ((lane >> 4) << 4);
    const uint32_t bOff = (uint32_t)(wn*32 + ((lane >> 3) & 1)*8 + (lane & 7)) * 144 + ((lane >> 4) << 4);

    #pragma unroll
    for (int es = 0; es < 4; es++) {
        const uint32_t cb = es * 32;
        uint32_t ah[2][4], bh2[2][4];
        #pragma unroll
        for (int mt = 0; mt < 2; mt++)
            LDSM4(ah[mt], sQH + aOff + (uint32_t)mt*16*144 + cb);
        #pragma unroll
        for (int nt2 = 0; nt2 < 2; nt2++)
            LDSM4(bh2[nt2], sKH + bOff + (uint32_t)nt2*16*144 + cb);
        #pragma unroll
        for (int mt = 0; mt < 2; mt++)
            #pragma unroll
            for (int nt = 0; nt < 4; nt++)
                MMAF16(acc[mt][nt], ah[mt], bh2[nt>>1][nt&1], bh2[nt>>1][2+(nt&1)]);
    }

    const float scale = 0.35355339059327373f;  // 1/sqrt(8) batch-size quirk
    float* out = g_Sc + (size_t)h * S_ * S_;
    #pragma unroll
    for (int mt = 0; mt < 2; mt++) {
        #pragma unroll
        for (int half = 0; half < 2; half++) {
            const int q = qt*64 + wm*32 + mt*16 + (lane >> 2) + half*8;
            #pragma unroll
            for (int nt = 0; nt < 4; nt++) {
                const int k0 = kt*64 + wn*32 + nt*8 + (lane & 3)*2;
                float v0 = acc[mt][nt][half*2]     * scale;
                float v1 = acc[mt][nt][half*2 + 1] * scale;
                if (k0     > q || v0 == 0.0f) v0 = -1e9f;
                if (k0 + 1 > q || v1 == 0.0f) v1 = -1e9f;
                *(float2*)(out + (size_t)q * S_ + k0) = make_float2(v0, v1);
            }
        }
    }
}

// ---------------- softmax over heads -> fp16 attn (hi only), per-batch -----
__global__ void softmax_h_kernel(int b)
{
    const int k = blockIdx.x * 256 + threadIdx.x;
    const int q = blockIdx.y;
    const int kmax = ((q >> 6) + 1) << 6;
    if (k >= kmax) return;

    const size_t so = (size_t)q * S_ + k;
    const size_t hs = (size_t)S_ * S_;
    float s[H_];
    float m = -3.4e38f;
    #pragma unroll
    for (int h = 0; h < H_; h++) { s[h] = g_Sc[so + h * hs]; m = fmaxf(m, s[h]); }
    float Z = 0.f;
    #pragma unroll
    for (int h = 0; h < H_; h++) { s[h] = expf(s[h] - m); Z += s[h]; }
    const float inv = 1.0f / Z;
    const size_t ab = (size_t)b * H_ * S_ * S_ + so;
    #pragma unroll
    for (int h = 0; h < H_; h++)
        g_Ah[ab + h * hs] = __float2half_rn(s[h] * inv);
}

// ---------------- V tile sums (from transposed fp16 V) + prefix scan -------
__global__ void tilesum_kernel()
{
    const int blk = blockIdx.x;
    const int e = threadIdx.x;
    const int tt = blk & (NT_ - 1);
    const int bh = blk / NT_;
    const __half2* Vb = (const __half2*)(g_Vth + (((size_t)bh * 64 + e) << 10) + tt*64);
    float sum = 0.f;
    #pragma unroll
    for (int k = 0; k < 32; k++) {
        const __half2 v = Vb[k];
        sum += __half2float(v.x) + __half2float(v.y);
    }
    g_TS[((size_t)bh * NT_ + tt) * E_ + e] = sum;
}

__global__ void scan_kernel()
{
    const int id = blockIdx.x * 256 + threadIdx.x;
    const int e = id & 63, bh = id >> 6;
    float* P = g_P + (size_t)bh * (NT_ + 1) * E_;
    float p = 0.f;
    P[e] = 0.f;
    #pragma unroll
    for (int tt = 0; tt < NT_; tt++) {
        p += g_TS[((size_t)bh * NT_ + tt) * E_ + e];
        P[(tt + 1) * E_ + e] = p;
    }
}

// ---------------- attn @ V via mma + masked suffix -------------------------
// grid (qt, bh), block 128; epilogue writes PACKED fold-2048 AO operand
__global__ __launch_bounds__(128) void attnv_mma_kernel()
{
    const int qt = blockIdx.x, bh = blockIdx.y;
    const int b = bh >> 4, h = bh & 15;

    __shared__ __align__(16) char sm[2 * 64 * 144];
    const uint32_t sAH = smem_u32(sm);
    const uint32_t sVH = sAH + 9216;

    const int tid = threadIdx.x;
    const int lane = tid & 31, wid = tid >> 5;
    const int wm = wid >> 1, wn = wid & 1;

    float acc[2][4][4];
    #pragma unroll
    for (int a = 0; a < 2; a++)
        #pragma unroll
        for (int b2 = 0; b2 < 4; b2++)
            #pragma unroll
            for (int c = 0; c < 4; c++) acc[a][b2][c] = 0.f;

    const uint32_t aOff = (uint32_t)(wm*32 + (lane & 15)) * 144 + ((lane >> 4) << 4);
    const uint32_t bOff = (uint32_t)(wn*32 + ((lane >> 3) & 1)*8 + (lane & 7)) * 144 + ((lane >> 4) << 4);

    const __half* gAH0 = g_Ah + ((size_t)bh * 1024 + qt*64) * 1024;
    const __half* gVH0 = g_Vth + (size_t)bh * 64 * 1024;

    for (int kt = 0; kt <= qt; kt++) {
        __syncthreads();
        #pragma unroll
        for (int i = tid; i < 512; i += 128) {
            const int r = i >> 3, c = i & 7;
            const size_t go = (size_t)r * 1024 + kt*64 + c * 8;
            const uint32_t so = r * 144 + c * 16;
            *(uint4*)(sm + so)        = *(const uint4*)(gAH0 + go);
            *(uint4*)(sm + 9216 + so) = *(const uint4*)(gVH0 + go);
        }
        __syncthreads();

        #pragma unroll
        for (int ks = 0; ks < 4; ks++) {
            const uint32_t cb = ks * 32;
            uint32_t ah[2][4], vh[2][4];
            #pragma unroll
            for (int mt = 0; mt < 2; mt++)
                LDSM4(ah[mt], sAH + aOff + (uint32_t)mt*16*144 + cb);
            #pragma unroll
            for (int nt2 = 0; nt2 < 2; nt2++)
                LDSM4(vh[nt2], sVH + bOff + (uint32_t)nt2*16*144 + cb);
            #pragma unroll
            for (int mt = 0; mt < 2; mt++)
                #pragma unroll
                for (int nt = 0; nt < 4; nt++)
                    MMAF16(acc[mt][nt], ah[mt], vh[nt>>1][nt&1], vh[nt>>1][2+(nt&1)]);
        }
    }

    const float* P = g_P + (size_t)bh * (NT_ + 1) * E_;
    #pragma unroll
    for (int nt = 0; nt < 4; nt++) {
        const int e0 = wn*32 + nt*8 + (lane & 3)*2;
        const float s0 = (P[NT_*E_ + e0]     - P[(qt+1)*E_ + e0])     * 0.0625f;
        const float s1 = (P[NT_*E_ + e0 + 1] - P[(qt+1)*E_ + e0 + 1]) * 0.0625f;
        #pragma unroll
        for (int mt = 0; mt < 2; mt++) {
            #pragma unroll
            for (int half = 0; half < 2; half++) {
                const int q = wm*32 + mt*16 + (lane >> 2) + half*8;
                const float v0 = acc[mt][nt][half*2]     + s0;
                const float v1 = acc[mt][nt][half*2 + 1] + s1;
                const __half h0 = __float2half_rn(v0);
                const __half h1 = __float2half_rn(v1);
                const __half l0 = __float2half_rn(v0 - __half2float(h0));
                const __half l1 = __float2half_rn(v1 - __half2float(h1));
                __half* base = g_AOp + ((size_t)(b*1024 + qt*64 + q)) * KPO_ + h*64 + e0;
                *(__half2*)(base)        = __half2(h0, h1);
                *(__half2*)(base + 1024) = __half2(l0, l1);
            }
        }
    }
}

// ---------------- launch ---------------------------------------------------
extern "C" void kernel_launch(void* const* d_in, const int* in_sizes, int n_in,
                              void* d_out, int out_size)
{
    const float* X1 = (const float*)d_in[0];
    const float* X2 = (const float*)d_in[1];
    const float* Wq = (const float*)d_in[2];
    const float* bq = (const float*)d_in[3];
    const float* Wk = (const float*)d_in[4];
    const float* bk = (const float*)d_in[5];
    const float* Wv = (const float*)d_in[6];
    const float* bv = (const float*)d_in[7];
    const float* Wo = (const float*)d_in[8];
    const float* bo = (const float*)d_in[9];
    float* out = (float*)d_out;

    void *pX1h, *pX2h, *pAOp, *pWq, *pWk, *pWv, *pWop;
    void *pQh, *pKh, *pVth;
    cudaGetSymbolAddress(&pX1h, g_X1h); cudaGetSymbolAddress(&pX2h, g_X2h);
    cudaGetSymbolAddress(&pAOp, g_AOp);
    cudaGetSymbolAddress(&pWq, g_Wq); cudaGetSymbolAddress(&pWk, g_Wk);
    cudaGetSymbolAddress(&pWv, g_Wv); cudaGetSymbolAddress(&pWop, g_Wop);
    cudaGetSymbolAddress(&pQh, g_Qh); cudaGetSymbolAddress(&pKh, g_Kh);
    cudaGetSymbolAddress(&pVth, g_Vth);

    const uint32_t SMEM_G = 61440;
    cudaFuncSetAttribute(gemm_mma_kernel,
                         cudaFuncAttributeMaxDynamicSharedMemorySize, SMEM_G);

    const int n4x = BS_ * D_ / 4;
    cvt_h_kernel<<<n4x / 256, 256>>>(X1, (__half*)pX1h, n4x);
    cvt_h_kernel<<<n4x / 256, 256>>>(X2, (__half*)pX2h, n4x);

    const dim3 gT(32, 32), bT(32, 8);
    pack_w_kernel<<<gT, bT>>>(Wq, (__half*)pWq,  D_,   0);
    pack_w_kernel<<<gT, bT>>>(Wk, (__half*)pWk,  D_,   0);
    pack_w_kernel<<<gT, bT>>>(Wv, (__half*)pWv,  D_,   0);
    pack_w_kernel<<<gT, bT>>>(Wo, (__half*)pWop, KPO_, 1);

    const dim3 gG(HE_ / 128, BS_ / 128);
    // Q/K/V projections: plain K=1024 (fp16 output rounding dominates anyway)
    gemm_mma_kernel<<<gG, 256, SMEM_G>>>((__half*)pX1h, (__half*)pWq, bq,
                                         nullptr, (__half*)pQh, 2, D_);
    gemm_mma_kernel<<<gG, 256, SMEM_G>>>((__half*)pX2h, (__half*)pWk, bk,
                                         nullptr, (__half*)pKh, 2, D_);
    gemm_mma_kernel<<<gG, 256, SMEM_G>>>((__half*)pX2h, (__half*)pWv, bv,
                                         nullptr, (__half*)pVth, 3, D_);

    tilesum_kernel<<<B_ * H_ * NT_, 64>>>();
    scan_kernel<<<(B_ * H_ * E_) / 256, 256>>>();

    // per-batch scores -> softmax on a shared L2-resident scratch
    for (int b = 0; b < B_; b++) {
        scores_mma_kernel<<<dim3(NT_, NT_, H_), 128>>>(b);
        softmax_h_kernel<<<dim3(S_ / 256, S_, 1), 256>>>(b);
    }

    attnv_mma_kernel<<<dim3(NT_, B_ * H_), 128>>>();

    // output projection keeps fold-2048 (fp32 final output)
    gemm_mma_kernel<<<gG, 256, SMEM_G>>>((__half*)pAOp, (__half*)pWop, bo,
                                         out, nullptr, 0, KPO_);
}